// round 3
// baseline (speedup 1.0000x reference)
#include <cuda_runtime.h>
#include <cuda_bf16.h>
#include <math.h>

// Problem dims
#define BB 4
#define LL 5
#define CIN 64
#define HH 256
#define WW 128
#define NIMG 20           // B*L
#define CHW (CIN*HH*WW)   // 2097152

// Scratch (static device globals; no allocation)
__device__ float g_neigh[NIMG * CIN * HH * WW];      // 20x64x256x128
__device__ float g_c1[NIMG * 32 * 128 * 64];
__device__ float g_c2[NIMG * 64 * 64 * 32];
__device__ float g_pool[NIMG * 64];
__device__ float g_keys[NIMG * 256];
__device__ float g_attn[BB * LL];

// ---------------- f32x2 helpers (packed dual-FMA; PTX-only on sm_103a) ------
__device__ __forceinline__ unsigned long long pack2(float x, float y) {
    unsigned long long r;
    asm("mov.b64 %0, {%1,%2};" : "=l"(r) : "f"(x), "f"(y));
    return r;
}
__device__ __forceinline__ void ffma2(unsigned long long& d,
                                      unsigned long long a, unsigned long long b) {
    asm("fma.rn.f32x2 %0, %1, %2, %0;" : "+l"(d) : "l"(a), "l"(b));
}
__device__ __forceinline__ float2 upk(unsigned long long v) {
    float2 f;
    asm("mov.b64 {%0,%1}, %2;" : "=f"(f.x), "=f"(f.y) : "l"(v));
    return f;
}

// ---------------------------------------------------------------------------
// Kernel 1: affine grid + bilinear grid_sample (zero padding) -> g_neigh
// grid (256 h, 20 img), block 128 (w)
// ---------------------------------------------------------------------------
__global__ __launch_bounds__(128) void k_warp(const float* __restrict__ x,
                                              const float* __restrict__ nam) {
    int w = threadIdx.x;
    int h = blockIdx.x;
    int g = blockIdx.y;
    int b = g / LL, n = g % LL;
    const float* th = nam + ((size_t)(b * LL + 0) * LL + n) * 6;
    float t00 = th[0], t01 = th[1], t02 = th[2];
    float t10 = th[3], t11 = th[4], t12 = th[5];

    float gx = (w + 0.5f) * (2.0f / WW) - 1.0f;
    float gy = (h + 0.5f) * (2.0f / HH) - 1.0f;
    float gxx = t00 * gx + t01 * gy + t02;
    float gyy = t10 * gx + t11 * gy + t12;

    float xf = ((gxx + 1.0f) * WW - 1.0f) * 0.5f;
    float yf = ((gyy + 1.0f) * HH - 1.0f) * 0.5f;
    float x0f = floorf(xf), y0f = floorf(yf);
    int x0 = (int)x0f, y0 = (int)y0f;
    int x1 = x0 + 1, y1 = y0 + 1;
    float wx1 = xf - x0f, wy1 = yf - y0f;
    float wx0 = 1.0f - wx1, wy0 = 1.0f - wy1;

    bool vx0 = (x0 >= 0) & (x0 < WW), vx1 = (x1 >= 0) & (x1 < WW);
    bool vy0 = (y0 >= 0) & (y0 < HH), vy1 = (y1 >= 0) & (y1 < HH);
    int cx0 = min(max(x0, 0), WW - 1), cx1 = min(max(x1, 0), WW - 1);
    int cy0 = min(max(y0, 0), HH - 1), cy1 = min(max(y1, 0), HH - 1);

    float w00 = wx0 * wy0 * (float)(vx0 && vy0);
    float w10 = wx1 * wy0 * (float)(vx1 && vy0);
    float w01 = wx0 * wy1 * (float)(vx0 && vy1);
    float w11 = wx1 * wy1 * (float)(vx1 && vy1);

    int a00 = cy0 * WW + cx0;
    int a10 = cy0 * WW + cx1;
    int a01 = cy1 * WW + cx0;
    int a11 = cy1 * WW + cx1;

    const float* img = x + (size_t)g * CHW;
    float* outp = g_neigh + (size_t)g * CHW + h * WW + w;
#pragma unroll 8
    for (int c = 0; c < CIN; ++c) {
        const float* ic = img + c * (HH * WW);
        float v = w00 * __ldg(ic + a00) + w10 * __ldg(ic + a10) +
                  w01 * __ldg(ic + a01) + w11 * __ldg(ic + a11);
        outp[c * (HH * WW)] = v;
    }
}

// ---------------------------------------------------------------------------
// zero pool accumulator
// ---------------------------------------------------------------------------
__global__ void k_zero() {
    int i = blockIdx.x * blockDim.x + threadIdx.x;
    if (i < NIMG * 64) g_pool[i] = 0.0f;
}

// ---------------------------------------------------------------------------
// Kernel 2: conv1 64->32, 4x4, s2, p1, ReLU. 256x128 -> 128x64 per image
// f32x2: thread computes pixel pair (2 adjacent ow) x 32 oc
// block 128 = 32 owPairs x 4 oh ; grid (32 ohTiles, 20 img)
// ---------------------------------------------------------------------------
__global__ __launch_bounds__(128) void k_conv1(const float* __restrict__ w1,
                                               const float* __restrict__ b1) {
    __shared__ float s_in[4][10][132];
    __shared__ ulonglong2 s_w[4 * 4 * 32 * 2];   // [(ci*4+kh)*32+oc]*2 + half

    int tid = threadIdx.x;
    int tp = tid & 31;           // ow pair idx -> ow0 = 2*tp
    int oh_l = tid >> 5;         // 0..3
    int oh0 = blockIdx.x * 4;
    int g = blockIdx.y;
    const float* in = g_neigh + (size_t)g * CHW;

    unsigned long long acc[32];
#pragma unroll
    for (int i = 0; i < 32; ++i) acc[i] = 0ull;

    for (int cc = 0; cc < 64; cc += 4) {
        // weights: splat (w,w) pairs
        for (int idx = tid; idx < 512; idx += 128) {
            int oc = idx & 31, kh = (idx >> 5) & 3, ci = idx >> 7;
            const float* wp = w1 + (((size_t)oc * 64 + cc + ci) * 4 + kh) * 4;
            float q0 = wp[0], q1 = wp[1], q2 = wp[2], q3 = wp[3];
            ulonglong2 lo, hi;
            lo.x = pack2(q0, q0); lo.y = pack2(q1, q1);
            hi.x = pack2(q2, q2); hi.y = pack2(q3, q3);
            s_w[idx * 2] = lo; s_w[idx * 2 + 1] = hi;
        }
        // input tile (rows 10 = 2*4+2 halo; cols 130)
        for (int idx = tid; idx < 4 * 10 * 130; idx += 128) {
            int j = idx % 130, r = (idx / 130) % 10, ci = idx / 1300;
            int ih = 2 * oh0 - 1 + r, iw = j - 1;
            float v = 0.0f;
            if (ih >= 0 && ih < HH && iw >= 0 && iw < WW)
                v = in[(size_t)(cc + ci) * (HH * WW) + ih * WW + iw];
            s_in[ci][r][j] = v;
        }
        __syncthreads();
#pragma unroll
        for (int ci = 0; ci < 4; ++ci) {
#pragma unroll
            for (int kh = 0; kh < 4; ++kh) {
                int r = 2 * oh_l + kh;
                const float* row = &s_in[ci][r][4 * tp];
                float2 A = *(const float2*)(row);
                float2 Bv = *(const float2*)(row + 2);
                float2 Cv = *(const float2*)(row + 4);
                unsigned long long pk0 = pack2(A.x, Bv.x);
                unsigned long long pk1 = pack2(A.y, Bv.y);
                unsigned long long pk2 = pack2(Bv.x, Cv.x);
                unsigned long long pk3 = pack2(Bv.y, Cv.y);
                const ulonglong2* wb = &s_w[((ci * 4 + kh) * 32) * 2];
#pragma unroll
                for (int oc = 0; oc < 32; ++oc) {
                    ulonglong2 w01 = wb[oc * 2];
                    ulonglong2 w23 = wb[oc * 2 + 1];
                    ffma2(acc[oc], pk0, w01.x);
                    ffma2(acc[oc], pk1, w01.y);
                    ffma2(acc[oc], pk2, w23.x);
                    ffma2(acc[oc], pk3, w23.y);
                }
            }
        }
        __syncthreads();
    }
    int oh = oh0 + oh_l;
    float* op = g_c1 + (size_t)g * 32 * 128 * 64 + oh * 64 + 2 * tp;
#pragma unroll
    for (int oc = 0; oc < 32; ++oc) {
        float bb = b1[oc];
        float2 r = upk(acc[oc]);
        float2 o;
        o.x = fmaxf(r.x + bb, 0.0f);
        o.y = fmaxf(r.y + bb, 0.0f);
        *(float2*)(op + (size_t)oc * 128 * 64) = o;
    }
}

// ---------------------------------------------------------------------------
// Kernel 3: conv2 32->64, 4x4, s2, p1, ReLU. 128x64 -> 64x32
// f32x2: thread = pixel pair x 32 oc (ocg splits 64 oc into 2)
// block 128 = 16 owPairs x 8 oh ; grid (8 ohTiles, 2 ocg, 20 img)
// ---------------------------------------------------------------------------
__global__ __launch_bounds__(128) void k_conv2(const float* __restrict__ w2,
                                               const float* __restrict__ b2) {
    __shared__ float s_in[4][18][68];
    __shared__ ulonglong2 s_w[4 * 4 * 32 * 2];

    int tid = threadIdx.x;
    int tp = tid & 15;           // ow0 = 2*tp (32 ow total)
    int oh_l = tid >> 4;         // 0..7
    int oh0 = blockIdx.x * 8;
    int ocb = blockIdx.y * 32;
    int g = blockIdx.z;
    const float* in = g_c1 + (size_t)g * 32 * 128 * 64;

    unsigned long long acc[32];
#pragma unroll
    for (int i = 0; i < 32; ++i) acc[i] = 0ull;

    for (int cc = 0; cc < 32; cc += 4) {
        for (int idx = tid; idx < 512; idx += 128) {
            int oc = idx & 31, kh = (idx >> 5) & 3, ci = idx >> 7;
            const float* wp = w2 + (((size_t)(ocb + oc) * 32 + cc + ci) * 4 + kh) * 4;
            float q0 = wp[0], q1 = wp[1], q2 = wp[2], q3 = wp[3];
            ulonglong2 lo, hi;
            lo.x = pack2(q0, q0); lo.y = pack2(q1, q1);
            hi.x = pack2(q2, q2); hi.y = pack2(q3, q3);
            s_w[idx * 2] = lo; s_w[idx * 2 + 1] = hi;
        }
        for (int idx = tid; idx < 4 * 18 * 66; idx += 128) {
            int j = idx % 66, r = (idx / 66) % 18, ci = idx / 1188;
            int ih = 2 * oh0 - 1 + r, iw = j - 1;
            float v = 0.0f;
            if (ih >= 0 && ih < 128 && iw >= 0 && iw < 64)
                v = in[(size_t)(cc + ci) * (128 * 64) + ih * 64 + iw];
            s_in[ci][r][j] = v;
        }
        __syncthreads();
#pragma unroll
        for (int ci = 0; ci < 4; ++ci) {
#pragma unroll
            for (int kh = 0; kh < 4; ++kh) {
                int r = 2 * oh_l + kh;
                const float* row = &s_in[ci][r][4 * tp];
                float2 A = *(const float2*)(row);
                float2 Bv = *(const float2*)(row + 2);
                float2 Cv = *(const float2*)(row + 4);
                unsigned long long pk0 = pack2(A.x, Bv.x);
                unsigned long long pk1 = pack2(A.y, Bv.y);
                unsigned long long pk2 = pack2(Bv.x, Cv.x);
                unsigned long long pk3 = pack2(Bv.y, Cv.y);
                const ulonglong2* wb = &s_w[((ci * 4 + kh) * 32) * 2];
#pragma unroll
                for (int oc = 0; oc < 32; ++oc) {
                    ulonglong2 w01 = wb[oc * 2];
                    ulonglong2 w23 = wb[oc * 2 + 1];
                    ffma2(acc[oc], pk0, w01.x);
                    ffma2(acc[oc], pk1, w01.y);
                    ffma2(acc[oc], pk2, w23.x);
                    ffma2(acc[oc], pk3, w23.y);
                }
            }
        }
        __syncthreads();
    }
    int oh = oh0 + oh_l;
    float* op = g_c2 + (size_t)g * 64 * 64 * 32 + oh * 32 + 2 * tp;
#pragma unroll
    for (int oc = 0; oc < 32; ++oc) {
        float bb = b2[ocb + oc];
        float2 r = upk(acc[oc]);
        float2 o;
        o.x = fmaxf(r.x + bb, 0.0f);
        o.y = fmaxf(r.y + bb, 0.0f);
        *(float2*)(op + (size_t)(ocb + oc) * 64 * 32) = o;
    }
}

// ---------------------------------------------------------------------------
// Kernel 4: conv3 64->64, 4x4, s2, p1 + ReLU, FUSED with global mean pool.
// Spatial output (32x16) is only ever consumed via mean -> never materialized.
// block 128 = 8 owPairs x 16 oh ; grid (2 ohTiles, 4 ocg(16 oc), 20 img)
// Each block reduces its ReLU'd outputs and atomicAdds into g_pool.
// ---------------------------------------------------------------------------
__global__ __launch_bounds__(128) void k_conv3pool(const float* __restrict__ w3,
                                                   const float* __restrict__ b3) {
    __shared__ float s_in[4][34][40];
    __shared__ ulonglong2 s_w[4 * 4 * 16 * 2];
    __shared__ float s_red[16][128];

    int tid = threadIdx.x;
    int tp = tid & 7;            // ow0 = 2*tp (16 ow total)
    int oh_l = tid >> 3;         // 0..15
    int oh0 = blockIdx.x * 16;
    int ocb = blockIdx.y * 16;
    int g = blockIdx.z;
    const float* in = g_c2 + (size_t)g * 64 * 64 * 32;

    unsigned long long acc[16];
#pragma unroll
    for (int i = 0; i < 16; ++i) acc[i] = 0ull;

    for (int cc = 0; cc < 64; cc += 4) {
        for (int idx = tid; idx < 256; idx += 128) {
            int oc = idx & 15, kh = (idx >> 4) & 3, ci = idx >> 6;
            const float* wp = w3 + (((size_t)(ocb + oc) * 64 + cc + ci) * 4 + kh) * 4;
            float q0 = wp[0], q1 = wp[1], q2 = wp[2], q3 = wp[3];
            ulonglong2 lo, hi;
            lo.x = pack2(q0, q0); lo.y = pack2(q1, q1);
            hi.x = pack2(q2, q2); hi.y = pack2(q3, q3);
            s_w[idx * 2] = lo; s_w[idx * 2 + 1] = hi;
        }
        for (int idx = tid; idx < 4 * 34 * 34; idx += 128) {
            int j = idx % 34, r = (idx / 34) % 34, ci = idx / 1156;
            int ih = 2 * oh0 - 1 + r, iw = j - 1;
            float v = 0.0f;
            if (ih >= 0 && ih < 64 && iw >= 0 && iw < 32)
                v = in[(size_t)(cc + ci) * (64 * 32) + ih * 32 + iw];
            s_in[ci][r][j] = v;
        }
        __syncthreads();
#pragma unroll
        for (int ci = 0; ci < 4; ++ci) {
#pragma unroll
            for (int kh = 0; kh < 4; ++kh) {
                int r = 2 * oh_l + kh;
                const float* row = &s_in[ci][r][4 * tp];
                float2 A = *(const float2*)(row);
                float2 Bv = *(const float2*)(row + 2);
                float2 Cv = *(const float2*)(row + 4);
                unsigned long long pk0 = pack2(A.x, Bv.x);
                unsigned long long pk1 = pack2(A.y, Bv.y);
                unsigned long long pk2 = pack2(Bv.x, Cv.x);
                unsigned long long pk3 = pack2(Bv.y, Cv.y);
                const ulonglong2* wb = &s_w[((ci * 4 + kh) * 16) * 2];
#pragma unroll
                for (int oc = 0; oc < 16; ++oc) {
                    ulonglong2 w01 = wb[oc * 2];
                    ulonglong2 w23 = wb[oc * 2 + 1];
                    ffma2(acc[oc], pk0, w01.x);
                    ffma2(acc[oc], pk1, w01.y);
                    ffma2(acc[oc], pk2, w23.x);
                    ffma2(acc[oc], pk3, w23.y);
                }
            }
        }
        __syncthreads();
    }
    // bias + relu + local pair-sum -> block reduction
#pragma unroll
    for (int oc = 0; oc < 16; ++oc) {
        float bb = b3[ocb + oc];
        float2 r = upk(acc[oc]);
        float v0 = fmaxf(r.x + bb, 0.0f);
        float v1 = fmaxf(r.y + bb, 0.0f);
        s_red[oc][tid] = v0 + v1;
    }
    __syncthreads();
    int wid = tid >> 5, lane = tid & 31;
#pragma unroll
    for (int k = 0; k < 4; ++k) {
        int oc = wid * 4 + k;
        float s = s_red[oc][lane] + s_red[oc][lane + 32] +
                  s_red[oc][lane + 64] + s_red[oc][lane + 96];
#pragma unroll
        for (int o = 16; o; o >>= 1) s += __shfl_xor_sync(0xFFFFFFFFu, s, o);
        if (lane == 0)
            atomicAdd(&g_pool[g * 64 + ocb + oc], s * (1.0f / 512.0f));
    }
}

// ---------------------------------------------------------------------------
// Kernel 5: key MLP 64->256->128->256 per image (grid 20, block 256)
// ---------------------------------------------------------------------------
__global__ __launch_bounds__(256) void k_keys(const float* __restrict__ f1w, const float* __restrict__ f1b,
                                              const float* __restrict__ f2w, const float* __restrict__ f2b,
                                              const float* __restrict__ f3w, const float* __restrict__ f3b) {
    __shared__ float p[64], h1[256], h2[128];
    int g = blockIdx.x, tid = threadIdx.x;
    if (tid < 64) p[tid] = g_pool[g * 64 + tid];
    __syncthreads();
    {
        float s = f1b[tid];
        const float* wr = f1w + (size_t)tid * 64;
#pragma unroll 8
        for (int c = 0; c < 64; ++c) s += wr[c] * p[c];
        h1[tid] = fmaxf(s, 0.0f);
    }
    __syncthreads();
    if (tid < 128) {
        float s = f2b[tid];
        const float* wr = f2w + (size_t)tid * 256;
#pragma unroll 8
        for (int c = 0; c < 256; ++c) s += wr[c] * h1[c];
        h2[tid] = fmaxf(s, 0.0f);
    }
    __syncthreads();
    {
        float s = f3b[tid];
        const float* wr = f3w + (size_t)tid * 128;
#pragma unroll 8
        for (int c = 0; c < 128; ++c) s += wr[c] * h2[c];
        g_keys[g * 256 + tid] = s;
    }
}

// ---------------------------------------------------------------------------
// Kernel 6: query MLP (image b*L), attn projection, softmax over L
// grid 4 (batch), block 256
// ---------------------------------------------------------------------------
__global__ __launch_bounds__(256) void k_attn(const float* __restrict__ f1w, const float* __restrict__ f1b,
                                              const float* __restrict__ f2w, const float* __restrict__ f2b,
                                              const float* __restrict__ f3w, const float* __restrict__ f3b,
                                              const float* __restrict__ aw, const float* __restrict__ ab) {
    __shared__ float p[64], h1[256], h2[128], qv[32], q[256], logits[8];
    int b = blockIdx.x, tid = threadIdx.x;
    int g0 = b * LL;
    if (tid < 64) p[tid] = g_pool[g0 * 64 + tid];
    __syncthreads();
    {
        float s = f1b[tid];
        const float* wr = f1w + (size_t)tid * 64;
#pragma unroll 8
        for (int c = 0; c < 64; ++c) s += wr[c] * p[c];
        h1[tid] = fmaxf(s, 0.0f);
    }
    __syncthreads();
    if (tid < 128) {
        float s = f2b[tid];
        const float* wr = f2w + (size_t)tid * 256;
#pragma unroll 8
        for (int c = 0; c < 256; ++c) s += wr[c] * h1[c];
        h2[tid] = fmaxf(s, 0.0f);
    }
    __syncthreads();
    if (tid < 32) {
        float s = f3b[tid];
        const float* wr = f3w + (size_t)tid * 128;
#pragma unroll 8
        for (int c = 0; c < 128; ++c) s += wr[c] * h2[c];
        qv[tid] = s;
    }
    __syncthreads();
    {
        float s = ab[tid];
        const float* wr = aw + (size_t)tid * 32;
#pragma unroll
        for (int j = 0; j < 32; ++j) s += wr[j] * qv[j];
        q[tid] = s;
    }
    __syncthreads();
    int wid = tid >> 5, lane = tid & 31;
    if (wid < LL) {
        const float* kr = g_keys + (size_t)(g0 + wid) * 256;
        float s = 0.0f;
        for (int i = lane; i < 256; i += 32) s += kr[i] * q[i];
#pragma unroll
        for (int o = 16; o; o >>= 1) s += __shfl_xor_sync(0xFFFFFFFFu, s, o);
        if (lane == 0) logits[wid] = s;
    }
    __syncthreads();
    if (tid == 0) {
        float m = -1e30f;
        for (int n = 0; n < LL; ++n) m = fmaxf(m, logits[n]);
        float e[LL];
        float den = 0.0f;
        for (int n = 0; n < LL; ++n) { e[n] = expf(logits[n] - m); den += e[n]; }
        float inv = 1.0f / den;
        for (int n = 0; n < LL; ++n) g_attn[b * LL + n] = e[n] * inv;
    }
}

// ---------------------------------------------------------------------------
// Kernel 7: out[b] = sum_n attn[b][n] * neigh[b*L+n]   (float4 vectorized)
// ---------------------------------------------------------------------------
__global__ __launch_bounds__(256) void k_fuse(float* __restrict__ out) {
    int b = blockIdx.y;
    int i = blockIdx.x * blockDim.x + threadIdx.x;   // float4 index
    float a0 = g_attn[b * LL + 0];
    float a1 = g_attn[b * LL + 1];
    float a2 = g_attn[b * LL + 2];
    float a3 = g_attn[b * LL + 3];
    float a4 = g_attn[b * LL + 4];
    const float4* n0 = reinterpret_cast<const float4*>(g_neigh + (size_t)(b * LL + 0) * CHW);
    const float4* n1 = reinterpret_cast<const float4*>(g_neigh + (size_t)(b * LL + 1) * CHW);
    const float4* n2 = reinterpret_cast<const float4*>(g_neigh + (size_t)(b * LL + 2) * CHW);
    const float4* n3 = reinterpret_cast<const float4*>(g_neigh + (size_t)(b * LL + 3) * CHW);
    const float4* n4 = reinterpret_cast<const float4*>(g_neigh + (size_t)(b * LL + 4) * CHW);
    float4 v0 = n0[i], v1 = n1[i], v2 = n2[i], v3 = n3[i], v4 = n4[i];
    float4 r;
    r.x = a0 * v0.x + a1 * v1.x + a2 * v2.x + a3 * v3.x + a4 * v4.x;
    r.y = a0 * v0.y + a1 * v1.y + a2 * v2.y + a3 * v3.y + a4 * v4.y;
    r.z = a0 * v0.z + a1 * v1.z + a2 * v2.z + a3 * v3.z + a4 * v4.z;
    r.w = a0 * v0.w + a1 * v1.w + a2 * v2.w + a3 * v3.w + a4 * v4.w;
    reinterpret_cast<float4*>(out + (size_t)b * CHW)[i] = r;
}

// ---------------------------------------------------------------------------
extern "C" void kernel_launch(void* const* d_in, const int* in_sizes, int n_in,
                              void* d_out, int out_size) {
    const float* x    = (const float*)d_in[0];
    const float* nam  = (const float*)d_in[2];
    const float* w1   = (const float*)d_in[3];
    const float* b1   = (const float*)d_in[4];
    const float* w2   = (const float*)d_in[5];
    const float* b2   = (const float*)d_in[6];
    const float* w3   = (const float*)d_in[7];
    const float* b3   = (const float*)d_in[8];
    const float* kf1w = (const float*)d_in[9];
    const float* kf1b = (const float*)d_in[10];
    const float* kf2w = (const float*)d_in[11];
    const float* kf2b = (const float*)d_in[12];
    const float* kf3w = (const float*)d_in[13];
    const float* kf3b = (const float*)d_in[14];
    const float* qf1w = (const float*)d_in[15];
    const float* qf1b = (const float*)d_in[16];
    const float* qf2w = (const float*)d_in[17];
    const float* qf2b = (const float*)d_in[18];
    const float* qf3w = (const float*)d_in[19];
    const float* qf3b = (const float*)d_in[20];
    const float* aw   = (const float*)d_in[21];
    const float* ab   = (const float*)d_in[22];
    float* out = (float*)d_out;

    k_zero     <<<5, 256>>>();
    k_warp     <<<dim3(HH, NIMG), 128>>>(x, nam);
    k_conv1    <<<dim3(32, NIMG), 128>>>(w1, b1);
    k_conv2    <<<dim3(8, 2, NIMG), 128>>>(w2, b2);
    k_conv3pool<<<dim3(2, 4, NIMG), 128>>>(w3, b3);
    k_keys     <<<NIMG, 256>>>(kf1w, kf1b, kf2w, kf2b, kf3w, kf3b);
    k_attn     <<<BB, 256>>>(qf1w, qf1b, qf2w, qf2b, qf3w, qf3b, aw, ab);
    k_fuse     <<<dim3(CHW / 4 / 256, BB), 256>>>(out);
}

// round 5
// speedup vs baseline: 1.7330x; 1.7330x over previous
#include <cuda_runtime.h>
#include <cuda_bf16.h>
#include <math.h>

// Problem dims
#define BB 4
#define LL 5
#define CIN 64
#define HH 256
#define WW 128
#define NIMG 20           // B*L
#define CHW (CIN*HH*WW)   // 2097152

// Scratch (static device globals; no allocation)
__device__ float g_neigh[NIMG * CIN * HH * WW];      // 20x64x256x128
__device__ float g_c1[NIMG * 32 * 128 * 64];
__device__ float g_c2[NIMG * 64 * 64 * 32];
__device__ float g_pool[NIMG * 64];
__device__ float g_keys[NIMG * 256];
__device__ float g_attn[BB * LL];

// ---------------- tf32 mma helpers --------------------------------------
__device__ __forceinline__ void mma8(float* d, const unsigned* a, const unsigned* b) {
    asm volatile(
        "mma.sync.aligned.m16n8k8.row.col.f32.tf32.tf32.f32 "
        "{%0,%1,%2,%3},{%4,%5,%6,%7},{%8,%9},{%0,%1,%2,%3};"
        : "+f"(d[0]), "+f"(d[1]), "+f"(d[2]), "+f"(d[3])
        : "r"(a[0]), "r"(a[1]), "r"(a[2]), "r"(a[3]), "r"(b[0]), "r"(b[1]));
}
__device__ __forceinline__ unsigned to_tf32(float v) {
    unsigned u;
    asm("cvt.rna.tf32.f32 %0, %1;" : "=r"(u) : "f"(v));
    return u;
}

// ---------------------------------------------------------------------------
// Kernel 1: affine grid + bilinear grid_sample (zero padding) -> g_neigh
// ---------------------------------------------------------------------------
__global__ __launch_bounds__(128) void k_warp(const float* __restrict__ x,
                                              const float* __restrict__ nam) {
    int w = threadIdx.x;
    int h = blockIdx.x;
    int g = blockIdx.y;
    int b = g / LL, n = g % LL;
    const float* th = nam + ((size_t)(b * LL + 0) * LL + n) * 6;
    float t00 = th[0], t01 = th[1], t02 = th[2];
    float t10 = th[3], t11 = th[4], t12 = th[5];

    float gx = (w + 0.5f) * (2.0f / WW) - 1.0f;
    float gy = (h + 0.5f) * (2.0f / HH) - 1.0f;
    float gxx = t00 * gx + t01 * gy + t02;
    float gyy = t10 * gx + t11 * gy + t12;

    float xf = ((gxx + 1.0f) * WW - 1.0f) * 0.5f;
    float yf = ((gyy + 1.0f) * HH - 1.0f) * 0.5f;
    float x0f = floorf(xf), y0f = floorf(yf);
    int x0 = (int)x0f, y0 = (int)y0f;
    int x1 = x0 + 1, y1 = y0 + 1;
    float wx1 = xf - x0f, wy1 = yf - y0f;
    float wx0 = 1.0f - wx1, wy0 = 1.0f - wy1;

    bool vx0 = (x0 >= 0) & (x0 < WW), vx1 = (x1 >= 0) & (x1 < WW);
    bool vy0 = (y0 >= 0) & (y0 < HH), vy1 = (y1 >= 0) & (y1 < HH);
    int cx0 = min(max(x0, 0), WW - 1), cx1 = min(max(x1, 0), WW - 1);
    int cy0 = min(max(y0, 0), HH - 1), cy1 = min(max(y1, 0), HH - 1);

    float w00 = wx0 * wy0 * (float)(vx0 && vy0);
    float w10 = wx1 * wy0 * (float)(vx1 && vy0);
    float w01 = wx0 * wy1 * (float)(vx0 && vy1);
    float w11 = wx1 * wy1 * (float)(vx1 && vy1);

    int a00 = cy0 * WW + cx0;
    int a10 = cy0 * WW + cx1;
    int a01 = cy1 * WW + cx0;
    int a11 = cy1 * WW + cx1;

    const float* img = x + (size_t)g * CHW;
    float* outp = g_neigh + (size_t)g * CHW + h * WW + w;
#pragma unroll 8
    for (int c = 0; c < CIN; ++c) {
        const float* ic = img + c * (HH * WW);
        float v = w00 * __ldg(ic + a00) + w10 * __ldg(ic + a10) +
                  w01 * __ldg(ic + a01) + w11 * __ldg(ic + a11);
        outp[c * (HH * WW)] = v;
    }
}

// ---------------------------------------------------------------------------
__global__ void k_zero() {
    int i = blockIdx.x * blockDim.x + threadIdx.x;
    if (i < NIMG * 64) g_pool[i] = 0.0f;
}

// ---------------------------------------------------------------------------
// Kernel 2: conv1 64->32, 4x4, s2, p1, ReLU.  256x128 -> 128x64
// Implicit GEMM via tf32 mma. Block tile: 256 px (oh8 x ow32) x 32 oc.
// grid (32 tiles [16 oh x 2 ow], 20 img), block 256 (8 warps).
// warp w handles oh row w, m-frags at ow {0,16}; K = 64ci*16taps.
// ---------------------------------------------------------------------------
__global__ __launch_bounds__(256) void k_conv1(const float* __restrict__ w1,
                                               const float* __restrict__ b1) {
    __shared__ float s_in[4][18][66];      // 4 ci, ih halo 18, iw halo 66
    __shared__ unsigned s_w[4][16][33];    // [ci][k][oc] tf32, pad 33

    int tid = threadIdx.x;
    int warp = tid >> 5, t = tid & 31;
    int r = t >> 2, c = t & 3;
    int tile = blockIdx.x;
    int g = blockIdx.y;
    int oh0 = (tile >> 1) * 8;
    int ow0 = (tile & 1) * 32;
    const float* in = g_neigh + (size_t)g * CHW;

    float acc[2][4][4];
#pragma unroll
    for (int mf = 0; mf < 2; ++mf)
#pragma unroll
        for (int nf = 0; nf < 4; ++nf)
#pragma unroll
            for (int i = 0; i < 4; ++i) acc[mf][nf][i] = 0.0f;

    for (int cc = 0; cc < 64; cc += 4) {
        for (int idx = tid; idx < 2048; idx += 256) {
            int oc = idx & 31, k = (idx >> 5) & 15, ci = idx >> 9;
            float v = w1[((size_t)(oc * 64 + cc + ci) * 4 + (k >> 2)) * 4 + (k & 3)];
            s_w[ci][k][oc] = to_tf32(v);
        }
        for (int idx = tid; idx < 4752; idx += 256) {
            int v = idx % 66, u = (idx / 66) % 18, ci = idx / 1188;
            int ih = 2 * oh0 - 1 + u, iw = 2 * ow0 - 1 + v;
            float val = 0.0f;
            if (ih >= 0 && ih < HH && iw >= 0 && iw < WW)
                val = in[(size_t)(cc + ci) * (HH * WW) + ih * WW + iw];
            s_in[ci][u][v] = val;
        }
        __syncthreads();
#pragma unroll
        for (int ci = 0; ci < 4; ++ci) {
#pragma unroll
            for (int h = 0; h < 2; ++h) {
                int u0 = 2 * warp + 2 * h;
                unsigned a[2][4];
#pragma unroll
                for (int mf = 0; mf < 2; ++mf) {
                    int v0 = 32 * mf + 2 * r + c;
                    a[mf][0] = __float_as_uint(s_in[ci][u0][v0]);
                    a[mf][1] = __float_as_uint(s_in[ci][u0][v0 + 16]);
                    a[mf][2] = __float_as_uint(s_in[ci][u0 + 1][v0]);
                    a[mf][3] = __float_as_uint(s_in[ci][u0 + 1][v0 + 16]);
                }
#pragma unroll
                for (int nf = 0; nf < 4; ++nf) {
                    unsigned bfr[2];
                    bfr[0] = s_w[ci][8 * h + c][8 * nf + r];
                    bfr[1] = s_w[ci][8 * h + c + 4][8 * nf + r];
                    mma8(acc[0][nf], a[0], bfr);
                    mma8(acc[1][nf], a[1], bfr);
                }
            }
        }
        __syncthreads();
    }
    int oh = oh0 + warp;
#pragma unroll
    for (int mf = 0; mf < 2; ++mf) {
        int ow = ow0 + 16 * mf + r;
#pragma unroll
        for (int nf = 0; nf < 4; ++nf) {
            int oc = 8 * nf + 2 * c;
            float bi0 = __ldg(b1 + oc), bi1 = __ldg(b1 + oc + 1);
            float* base = g_c1 + ((size_t)(g * 32 + oc) * 128 + oh) * 64;
            base[ow]           = fmaxf(acc[mf][nf][0] + bi0, 0.0f);
            (base + 8192)[ow]  = fmaxf(acc[mf][nf][1] + bi1, 0.0f);
            base[ow + 8]          = fmaxf(acc[mf][nf][2] + bi0, 0.0f);
            (base + 8192)[ow + 8] = fmaxf(acc[mf][nf][3] + bi1, 0.0f);
        }
    }
}

// ---------------------------------------------------------------------------
// Kernel 3: conv2 32->64, 4x4, s2, p1, ReLU.  128x64 -> 64x32
// Block tile: 256 px (oh8 x ow32=full) x 64 oc. grid (8, 20).
// ---------------------------------------------------------------------------
__global__ __launch_bounds__(256) void k_conv2(const float* __restrict__ w2,
                                               const float* __restrict__ b2) {
    __shared__ float s_in[4][18][66];
    __shared__ unsigned s_w[4][16][65];

    int tid = threadIdx.x;
    int warp = tid >> 5, t = tid & 31;
    int r = t >> 2, c = t & 3;
    int oh0 = blockIdx.x * 8;
    int g = blockIdx.y;
    const float* in = g_c1 + (size_t)g * 32 * 128 * 64;

    float acc[2][8][4];
#pragma unroll
    for (int mf = 0; mf < 2; ++mf)
#pragma unroll
        for (int nf = 0; nf < 8; ++nf)
#pragma unroll
            for (int i = 0; i < 4; ++i) acc[mf][nf][i] = 0.0f;

    for (int cc = 0; cc < 32; cc += 4) {
        for (int idx = tid; idx < 4096; idx += 256) {
            int oc = idx & 63, k = (idx >> 6) & 15, ci = idx >> 10;
            float v = w2[((size_t)(oc * 32 + cc + ci) * 4 + (k >> 2)) * 4 + (k & 3)];
            s_w[ci][k][oc] = to_tf32(v);
        }
        for (int idx = tid; idx < 4752; idx += 256) {
            int v = idx % 66, u = (idx / 66) % 18, ci = idx / 1188;
            int ih = 2 * oh0 - 1 + u, iw = -1 + v;
            float val = 0.0f;
            if (ih >= 0 && ih < 128 && iw >= 0 && iw < 64)
                val = in[(size_t)(cc + ci) * (128 * 64) + ih * 64 + iw];
            s_in[ci][u][v] = val;
        }
        __syncthreads();
#pragma unroll
        for (int ci = 0; ci < 4; ++ci) {
#pragma unroll
            for (int h = 0; h < 2; ++h) {
                int u0 = 2 * warp + 2 * h;
                unsigned a[2][4];
#pragma unroll
                for (int mf = 0; mf < 2; ++mf) {
                    int v0 = 32 * mf + 2 * r + c;
                    a[mf][0] = __float_as_uint(s_in[ci][u0][v0]);
                    a[mf][1] = __float_as_uint(s_in[ci][u0][v0 + 16]);
                    a[mf][2] = __float_as_uint(s_in[ci][u0 + 1][v0]);
                    a[mf][3] = __float_as_uint(s_in[ci][u0 + 1][v0 + 16]);
                }
#pragma unroll
                for (int nf = 0; nf < 8; ++nf) {
                    unsigned bfr[2];
                    bfr[0] = s_w[ci][8 * h + c][8 * nf + r];
                    bfr[1] = s_w[ci][8 * h + c + 4][8 * nf + r];
                    mma8(acc[0][nf], a[0], bfr);
                    mma8(acc[1][nf], a[1], bfr);
                }
            }
        }
        __syncthreads();
    }
    int oh = oh0 + warp;
#pragma unroll
    for (int mf = 0; mf < 2; ++mf) {
        int ow = 16 * mf + r;
#pragma unroll
        for (int nf = 0; nf < 8; ++nf) {
            int oc = 8 * nf + 2 * c;
            float bi0 = __ldg(b2 + oc), bi1 = __ldg(b2 + oc + 1);
            float* base = g_c2 + ((size_t)(g * 64 + oc) * 64 + oh) * 32;
            base[ow]           = fmaxf(acc[mf][nf][0] + bi0, 0.0f);
            (base + 2048)[ow]  = fmaxf(acc[mf][nf][1] + bi1, 0.0f);
            base[ow + 8]          = fmaxf(acc[mf][nf][2] + bi0, 0.0f);
            (base + 2048)[ow + 8] = fmaxf(acc[mf][nf][3] + bi1, 0.0f);
        }
    }
}

// ---------------------------------------------------------------------------
// Kernel 4: conv3 64->64, 4x4, s2, p1 + ReLU, fused global mean pool.
// Block tile: 256 px (oh16 x ow16=full) x 64 oc. grid (2, 20).
// warp w handles oh rows {2w, 2w+1}. Reduces in registers -> atomicAdd.
// ---------------------------------------------------------------------------
__global__ __launch_bounds__(256) void k_conv3pool(const float* __restrict__ w3,
                                                   const float* __restrict__ b3) {
    __shared__ float s_in[4][34][34];
    __shared__ unsigned s_w[4][16][65];

    int tid = threadIdx.x;
    int warp = tid >> 5, t = tid & 31;
    int r = t >> 2, c = t & 3;
    int oh0 = blockIdx.x * 16;
    int g = blockIdx.y;
    const float* in = g_c2 + (size_t)g * 64 * 64 * 32;

    float acc[2][8][4];
#pragma unroll
    for (int mf = 0; mf < 2; ++mf)
#pragma unroll
        for (int nf = 0; nf < 8; ++nf)
#pragma unroll
            for (int i = 0; i < 4; ++i) acc[mf][nf][i] = 0.0f;

    for (int cc = 0; cc < 64; cc += 4) {
        for (int idx = tid; idx < 4096; idx += 256) {
            int oc = idx & 63, k = (idx >> 6) & 15, ci = idx >> 10;
            float v = w3[((size_t)(oc * 64 + cc + ci) * 4 + (k >> 2)) * 4 + (k & 3)];
            s_w[ci][k][oc] = to_tf32(v);
        }
        for (int idx = tid; idx < 4624; idx += 256) {
            int v = idx % 34, u = (idx / 34) % 34, ci = idx / 1156;
            int ih = 2 * oh0 - 1 + u, iw = -1 + v;
            float val = 0.0f;
            if (ih >= 0 && ih < 64 && iw >= 0 && iw < 32)
                val = in[(size_t)(cc + ci) * (64 * 32) + ih * 32 + iw];
            s_in[ci][u][v] = val;
        }
        __syncthreads();
#pragma unroll
        for (int ci = 0; ci < 4; ++ci) {
#pragma unroll
            for (int h = 0; h < 2; ++h) {
                unsigned a[2][4];
#pragma unroll
                for (int mf = 0; mf < 2; ++mf) {
                    int u0 = 4 * warp + 2 * mf + 2 * h;
                    int v0 = 2 * r + c;
                    a[mf][0] = __float_as_uint(s_in[ci][u0][v0]);
                    a[mf][1] = __float_as_uint(s_in[ci][u0][v0 + 16]);
                    a[mf][2] = __float_as_uint(s_in[ci][u0 + 1][v0]);
                    a[mf][3] = __float_as_uint(s_in[ci][u0 + 1][v0 + 16]);
                }
#pragma unroll
                for (int nf = 0; nf < 8; ++nf) {
                    unsigned bfr[2];
                    bfr[0] = s_w[ci][8 * h + c][8 * nf + r];
                    bfr[1] = s_w[ci][8 * h + c + 4][8 * nf + r];
                    mma8(acc[0][nf], a[0], bfr);
                    mma8(acc[1][nf], a[1], bfr);
                }
            }
        }
        __syncthreads();
    }
    // bias + relu + reduce over this warp's 32 px, then atomicAdd.
#pragma unroll
    for (int nf = 0; nf < 8; ++nf) {
        int oc0 = 8 * nf + 2 * c;
        float bi0 = __ldg(b3 + oc0), bi1 = __ldg(b3 + oc0 + 1);
        float s0 = 0.0f, s1 = 0.0f;
#pragma unroll
        for (int mf = 0; mf < 2; ++mf) {
            s0 += fmaxf(acc[mf][nf][0] + bi0, 0.0f) + fmaxf(acc[mf][nf][2] + bi0, 0.0f);
            s1 += fmaxf(acc[mf][nf][1] + bi1, 0.0f) + fmaxf(acc[mf][nf][3] + bi1, 0.0f);
        }
#pragma unroll
        for (int o = 4; o <= 16; o <<= 1) {
            s0 += __shfl_xor_sync(0xFFFFFFFFu, s0, o);
            s1 += __shfl_xor_sync(0xFFFFFFFFu, s1, o);
        }
        if (r == 0) {
            atomicAdd(&g_pool[g * 64 + oc0],     s0 * (1.0f / 512.0f));
            atomicAdd(&g_pool[g * 64 + oc0 + 1], s1 * (1.0f / 512.0f));
        }
    }
}

// ---------------------------------------------------------------------------
// Kernel 5: key MLP 64->256->128->256 per image (grid 20, block 256)
// ---------------------------------------------------------------------------
__global__ __launch_bounds__(256) void k_keys(const float* __restrict__ f1w, const float* __restrict__ f1b,
                                              const float* __restrict__ f2w, const float* __restrict__ f2b,
                                              const float* __restrict__ f3w, const float* __restrict__ f3b) {
    __shared__ float p[64], h1[256], h2[128];
    int g = blockIdx.x, tid = threadIdx.x;
    if (tid < 64) p[tid] = g_pool[g * 64 + tid];
    __syncthreads();
    {
        float s = f1b[tid];
        const float* wr = f1w + (size_t)tid * 64;
#pragma unroll 8
        for (int c = 0; c < 64; ++c) s += wr[c] * p[c];
        h1[tid] = fmaxf(s, 0.0f);
    }
    __syncthreads();
    if (tid < 128) {
        float s = f2b[tid];
        const float* wr = f2w + (size_t)tid * 256;
#pragma unroll 8
        for (int c = 0; c < 256; ++c) s += wr[c] * h1[c];
        h2[tid] = fmaxf(s, 0.0f);
    }
    __syncthreads();
    {
        float s = f3b[tid];
        const float* wr = f3w + (size_t)tid * 128;
#pragma unroll 8
        for (int c = 0; c < 128; ++c) s += wr[c] * h2[c];
        g_keys[g * 256 + tid] = s;
    }
}

// ---------------------------------------------------------------------------
// Kernel 6: query MLP (image b*L), attn projection, softmax over L
// ---------------------------------------------------------------------------
__global__ __launch_bounds__(256) void k_attn(const float* __restrict__ f1w, const float* __restrict__ f1b,
                                              const float* __restrict__ f2w, const float* __restrict__ f2b,
                                              const float* __restrict__ f3w, const float* __restrict__ f3b,
                                              const float* __restrict__ aw, const float* __restrict__ ab) {
    __shared__ float p[64], h1[256], h2[128], qv[32], q[256], logits[8];
    int b = blockIdx.x, tid = threadIdx.x;
    int g0 = b * LL;
    if (tid < 64) p[tid] = g_pool[g0 * 64 + tid];
    __syncthreads();
    {
        float s = f1b[tid];
        const float* wr = f1w + (size_t)tid * 64;
#pragma unroll 8
        for (int c = 0; c < 64; ++c) s += wr[c] * p[c];
        h1[tid] = fmaxf(s, 0.0f);
    }
    __syncthreads();
    if (tid < 128) {
        float s = f2b[tid];
        const float* wr = f2w + (size_t)tid * 256;
#pragma unroll 8
        for (int c = 0; c < 256; ++c) s += wr[c] * h1[c];
        h2[tid] = fmaxf(s, 0.0f);
    }
    __syncthreads();
    if (tid < 32) {
        float s = f3b[tid];
        const float* wr = f3w + (size_t)tid * 128;
#pragma unroll 8
        for (int c = 0; c < 128; ++c) s += wr[c] * h2[c];
        qv[tid] = s;
    }
    __syncthreads();
    {
        float s = ab[tid];
        const float* wr = aw + (size_t)tid * 32;
#pragma unroll
        for (int j = 0; j < 32; ++j) s += wr[j] * qv[j];
        q[tid] = s;
    }
    __syncthreads();
    int wid = tid >> 5, lane = tid & 31;
    if (wid < LL) {
        const float* kr = g_keys + (size_t)(g0 + wid) * 256;
        float s = 0.0f;
        for (int i = lane; i < 256; i += 32) s += kr[i] * q[i];
#pragma unroll
        for (int o = 16; o; o >>= 1) s += __shfl_xor_sync(0xFFFFFFFFu, s, o);
        if (lane == 0) logits[wid] = s;
    }
    __syncthreads();
    if (tid == 0) {
        float m = -1e30f;
        for (int n = 0; n < LL; ++n) m = fmaxf(m, logits[n]);
        float e[LL];
        float den = 0.0f;
        for (int n = 0; n < LL; ++n) { e[n] = expf(logits[n] - m); den += e[n]; }
        float inv = 1.0f / den;
        for (int n = 0; n < LL; ++n) g_attn[b * LL + n] = e[n] * inv;
    }
}

// ---------------------------------------------------------------------------
// Kernel 7: out[b] = sum_n attn[b][n] * neigh[b*L+n]   (float4 vectorized)
// ---------------------------------------------------------------------------
__global__ __launch_bounds__(256) void k_fuse(float* __restrict__ out) {
    int b = blockIdx.y;
    int i = blockIdx.x * blockDim.x + threadIdx.x;
    float a0 = g_attn[b * LL + 0];
    float a1 = g_attn[b * LL + 1];
    float a2 = g_attn[b * LL + 2];
    float a3 = g_attn[b * LL + 3];
    float a4 = g_attn[b * LL + 4];
    const float4* n0 = reinterpret_cast<const float4*>(g_neigh + (size_t)(b * LL + 0) * CHW);
    const float4* n1 = reinterpret_cast<const float4*>(g_neigh + (size_t)(b * LL + 1) * CHW);
    const float4* n2 = reinterpret_cast<const float4*>(g_neigh + (size_t)(b * LL + 2) * CHW);
    const float4* n3 = reinterpret_cast<const float4*>(g_neigh + (size_t)(b * LL + 3) * CHW);
    const float4* n4 = reinterpret_cast<const float4*>(g_neigh + (size_t)(b * LL + 4) * CHW);
    float4 v0 = n0[i], v1 = n1[i], v2 = n2[i], v3 = n3[i], v4 = n4[i];
    float4 r;
    r.x = a0 * v0.x + a1 * v1.x + a2 * v2.x + a3 * v3.x + a4 * v4.x;
    r.y = a0 * v0.y + a1 * v1.y + a2 * v2.y + a3 * v3.y + a4 * v4.y;
    r.z = a0 * v0.z + a1 * v1.z + a2 * v2.z + a3 * v3.z + a4 * v4.z;
    r.w = a0 * v0.w + a1 * v1.w + a2 * v2.w + a3 * v3.w + a4 * v4.w;
    reinterpret_cast<float4*>(out + (size_t)b * CHW)[i] = r;
}

// ---------------------------------------------------------------------------
extern "C" void kernel_launch(void* const* d_in, const int* in_sizes, int n_in,
                              void* d_out, int out_size) {
    const float* x    = (const float*)d_in[0];
    const float* nam  = (const float*)d_in[2];
    const float* w1   = (const float*)d_in[3];
    const float* b1   = (const float*)d_in[4];
    const float* w2   = (const float*)d_in[5];
    const float* b2   = (const float*)d_in[6];
    const float* w3   = (const float*)d_in[7];
    const float* b3   = (const float*)d_in[8];
    const float* kf1w = (const float*)d_in[9];
    const float* kf1b = (const float*)d_in[10];
    const float* kf2w = (const float*)d_in[11];
    const float* kf2b = (const float*)d_in[12];
    const float* kf3w = (const float*)d_in[13];
    const float* kf3b = (const float*)d_in[14];
    const float* qf1w = (const float*)d_in[15];
    const float* qf1b = (const float*)d_in[16];
    const float* qf2w = (const float*)d_in[17];
    const float* qf2b = (const float*)d_in[18];
    const float* qf3w = (const float*)d_in[19];
    const float* qf3b = (const float*)d_in[20];
    const float* aw   = (const float*)d_in[21];
    const float* ab   = (const float*)d_in[22];
    float* out = (float*)d_out;

    k_zero     <<<5, 256>>>();
    k_warp     <<<dim3(HH, NIMG), 128>>>(x, nam);
    k_conv1    <<<dim3(32, NIMG), 256>>>(w1, b1);
    k_conv2    <<<dim3(8, NIMG), 256>>>(w2, b2);
    k_conv3pool<<<dim3(2, NIMG), 256>>>(w3, b3);
    k_keys     <<<NIMG, 256>>>(kf1w, kf1b, kf2w, kf2b, kf3w, kf3b);
    k_attn     <<<BB, 256>>>(qf1w, qf1b, qf2w, qf2b, qf3w, qf3b, aw, ab);
    k_fuse     <<<dim3(CHW / 4 / 256, BB), 256>>>(out);
}

// round 6
// speedup vs baseline: 2.1201x; 1.2234x over previous
#include <cuda_runtime.h>
#include <cuda_bf16.h>
#include <math.h>

// Problem dims
#define BB 4
#define LL 5
#define CIN 64
#define HH 256
#define WW 128
#define NIMG 20           // B*L
#define CHW (CIN*HH*WW)   // 2097152

// Scratch (static device globals; no allocation)
__device__ float g_neigh[NIMG * CIN * HH * WW];      // 20x64x256x128
__device__ float g_c1[NIMG * 32 * 128 * 64];
__device__ float g_c2[NIMG * 64 * 64 * 32];
__device__ float g_pool[NIMG * 64];
__device__ float g_keys[NIMG * 256];
__device__ float g_attn[BB * LL];

// ---------------- tf32 mma + cp.async helpers ------------------------------
__device__ __forceinline__ void mma8(float* d, const unsigned* a, const unsigned* b) {
    asm volatile(
        "mma.sync.aligned.m16n8k8.row.col.f32.tf32.tf32.f32 "
        "{%0,%1,%2,%3},{%4,%5,%6,%7},{%8,%9},{%0,%1,%2,%3};"
        : "+f"(d[0]), "+f"(d[1]), "+f"(d[2]), "+f"(d[3])
        : "r"(a[0]), "r"(a[1]), "r"(a[2]), "r"(a[3]), "r"(b[0]), "r"(b[1]));
}
__device__ __forceinline__ void cpa4(unsigned dst, const float* src, bool ok) {
    asm volatile("cp.async.ca.shared.global [%0], [%1], 4, %2;"
                 :: "r"(dst), "l"(src), "r"(ok ? 4 : 0));
}
#define CP_COMMIT() asm volatile("cp.async.commit_group;")
#define CP_WAIT1()  asm volatile("cp.async.wait_group 1;")
#define CP_WAIT0()  asm volatile("cp.async.wait_group 0;")

// ---------------------------------------------------------------------------
// Kernel 1: affine grid + bilinear grid_sample (zero padding) -> g_neigh
// ---------------------------------------------------------------------------
__global__ __launch_bounds__(128) void k_warp(const float* __restrict__ x,
                                              const float* __restrict__ nam) {
    int w = threadIdx.x;
    int h = blockIdx.x;
    int g = blockIdx.y;
    int b = g / LL, n = g % LL;
    const float* th = nam + ((size_t)(b * LL + 0) * LL + n) * 6;
    float t00 = th[0], t01 = th[1], t02 = th[2];
    float t10 = th[3], t11 = th[4], t12 = th[5];

    float gx = (w + 0.5f) * (2.0f / WW) - 1.0f;
    float gy = (h + 0.5f) * (2.0f / HH) - 1.0f;
    float gxx = t00 * gx + t01 * gy + t02;
    float gyy = t10 * gx + t11 * gy + t12;

    float xf = ((gxx + 1.0f) * WW - 1.0f) * 0.5f;
    float yf = ((gyy + 1.0f) * HH - 1.0f) * 0.5f;
    float x0f = floorf(xf), y0f = floorf(yf);
    int x0 = (int)x0f, y0 = (int)y0f;
    int x1 = x0 + 1, y1 = y0 + 1;
    float wx1 = xf - x0f, wy1 = yf - y0f;
    float wx0 = 1.0f - wx1, wy0 = 1.0f - wy1;

    bool vx0 = (x0 >= 0) & (x0 < WW), vx1 = (x1 >= 0) & (x1 < WW);
    bool vy0 = (y0 >= 0) & (y0 < HH), vy1 = (y1 >= 0) & (y1 < HH);
    int cx0 = min(max(x0, 0), WW - 1), cx1 = min(max(x1, 0), WW - 1);
    int cy0 = min(max(y0, 0), HH - 1), cy1 = min(max(y1, 0), HH - 1);

    float w00 = wx0 * wy0 * (float)(vx0 && vy0);
    float w10 = wx1 * wy0 * (float)(vx1 && vy0);
    float w01 = wx0 * wy1 * (float)(vx0 && vy1);
    float w11 = wx1 * wy1 * (float)(vx1 && vy1);

    int a00 = cy0 * WW + cx0;
    int a10 = cy0 * WW + cx1;
    int a01 = cy1 * WW + cx0;
    int a11 = cy1 * WW + cx1;

    const float* img = x + (size_t)g * CHW;
    float* outp = g_neigh + (size_t)g * CHW + h * WW + w;
#pragma unroll 8
    for (int c = 0; c < CIN; ++c) {
        const float* ic = img + c * (HH * WW);
        float v = w00 * __ldg(ic + a00) + w10 * __ldg(ic + a10) +
                  w01 * __ldg(ic + a01) + w11 * __ldg(ic + a11);
        outp[c * (HH * WW)] = v;
    }
}

// ---------------------------------------------------------------------------
__global__ void k_zero() {
    int i = blockIdx.x * blockDim.x + threadIdx.x;
    if (i < NIMG * 64) g_pool[i] = 0.0f;
}

// ---------------------------------------------------------------------------
// Kernel 2: conv1 64->32, 4x4, s2, p1, ReLU.  256x128 -> 128x64
// tf32 implicit GEMM, cp.async double-buffered over 16 ci-chunks.
// Block 256 (8 warps): tile oh8 x ow32 x 32oc. grid (32, 20).
// ---------------------------------------------------------------------------
__global__ __launch_bounds__(256) void k_conv1(const float* __restrict__ w1,
                                               const float* __restrict__ b1) {
    __shared__ float s_in[2][4][18][66];
    __shared__ float s_w[2][4][16][33];

    int tid = threadIdx.x;
    int warp = tid >> 5, t = tid & 31;
    int r = t >> 2, c = t & 3;
    int tile = blockIdx.x;
    int g = blockIdx.y;
    int oh0 = (tile >> 1) * 8;
    int ow0 = (tile & 1) * 32;
    const float* in = g_neigh + (size_t)g * CHW;

    unsigned si_base = (unsigned)__cvta_generic_to_shared(&s_in[0][0][0][0]);
    unsigned sw_base = (unsigned)__cvta_generic_to_shared(&s_w[0][0][0][0]);

    float acc[2][4][4];
#pragma unroll
    for (int mf = 0; mf < 2; ++mf)
#pragma unroll
        for (int nf = 0; nf < 4; ++nf)
#pragma unroll
            for (int i = 0; i < 4; ++i) acc[mf][nf][i] = 0.0f;

#define C1_LOAD(Q, BUF)                                                          \
    {                                                                            \
        int cc = (Q) * 4;                                                        \
        for (int idx = tid; idx < 2048; idx += 256) {                            \
            int oc = idx & 31, k = (idx >> 5) & 15, ci = idx >> 9;               \
            unsigned dst = sw_base + ((((BUF)*4 + ci) * 16 + k) * 33 + oc) * 4;  \
            cpa4(dst, w1 + (size_t)(oc * 64 + cc + ci) * 16 + k, true);          \
        }                                                                        \
        for (int idx = tid; idx < 4752; idx += 256) {                            \
            int v = idx % 66, u = (idx / 66) % 18, ci = idx / 1188;              \
            int ih = 2 * oh0 - 1 + u, iw = 2 * ow0 - 1 + v;                      \
            bool ok = (ih >= 0) && (ih < HH) && (iw >= 0) && (iw < WW);          \
            const float* src = ok ? in + (size_t)(cc + ci) * (HH * WW) + ih * WW + iw : in; \
            unsigned dst = si_base + ((((BUF)*4 + ci) * 18 + u) * 66 + v) * 4;   \
            cpa4(dst, src, ok);                                                  \
        }                                                                        \
    }

    C1_LOAD(0, 0);
    CP_COMMIT();
    for (int q = 0; q < 16; ++q) {
        int buf = q & 1;
        if (q + 1 < 16) {
            C1_LOAD(q + 1, buf ^ 1);
            CP_COMMIT();
            CP_WAIT1();
        } else {
            CP_WAIT0();
        }
        __syncthreads();
#pragma unroll
        for (int ci = 0; ci < 4; ++ci) {
#pragma unroll
            for (int h = 0; h < 2; ++h) {
                int u0 = 2 * warp + 2 * h;
                unsigned a[2][4];
#pragma unroll
                for (int mf = 0; mf < 2; ++mf) {
                    int v0 = 32 * mf + 2 * r + c;
                    a[mf][0] = __float_as_uint(s_in[buf][ci][u0][v0]);
                    a[mf][1] = __float_as_uint(s_in[buf][ci][u0][v0 + 16]);
                    a[mf][2] = __float_as_uint(s_in[buf][ci][u0 + 1][v0]);
                    a[mf][3] = __float_as_uint(s_in[buf][ci][u0 + 1][v0 + 16]);
                }
#pragma unroll
                for (int nf = 0; nf < 4; ++nf) {
                    unsigned bfr[2];
                    bfr[0] = __float_as_uint(s_w[buf][ci][8 * h + c][8 * nf + r]);
                    bfr[1] = __float_as_uint(s_w[buf][ci][8 * h + c + 4][8 * nf + r]);
                    mma8(acc[0][nf], a[0], bfr);
                    mma8(acc[1][nf], a[1], bfr);
                }
            }
        }
        __syncthreads();
    }
    int oh = oh0 + warp;
#pragma unroll
    for (int mf = 0; mf < 2; ++mf) {
        int ow = ow0 + 16 * mf + r;
#pragma unroll
        for (int nf = 0; nf < 4; ++nf) {
            int oc = 8 * nf + 2 * c;
            float bi0 = __ldg(b1 + oc), bi1 = __ldg(b1 + oc + 1);
            float* base = g_c1 + ((size_t)(g * 32 + oc) * 128 + oh) * 64;
            base[ow]           = fmaxf(acc[mf][nf][0] + bi0, 0.0f);
            (base + 8192)[ow]  = fmaxf(acc[mf][nf][1] + bi1, 0.0f);
            base[ow + 8]          = fmaxf(acc[mf][nf][2] + bi0, 0.0f);
            (base + 8192)[ow + 8] = fmaxf(acc[mf][nf][3] + bi1, 0.0f);
        }
    }
#undef C1_LOAD
}

// ---------------------------------------------------------------------------
// Kernel 3: conv2 32->64, 4x4, s2, p1, ReLU.  128x64 -> 64x32
// Block 256: tile oh8 x ow32(full) x 32oc. grid (8 oh, 2 ocg, 20).
// cp.async double-buffered over 8 ci-chunks.
// ---------------------------------------------------------------------------
__global__ __launch_bounds__(256) void k_conv2(const float* __restrict__ w2,
                                               const float* __restrict__ b2) {
    __shared__ float s_in[2][4][18][66];
    __shared__ float s_w[2][4][16][33];

    int tid = threadIdx.x;
    int warp = tid >> 5, t = tid & 31;
    int r = t >> 2, c = t & 3;
    int oh0 = blockIdx.x * 8;
    int ocb = blockIdx.y * 32;
    int g = blockIdx.z;
    const float* in = g_c1 + (size_t)g * 32 * 128 * 64;

    unsigned si_base = (unsigned)__cvta_generic_to_shared(&s_in[0][0][0][0]);
    unsigned sw_base = (unsigned)__cvta_generic_to_shared(&s_w[0][0][0][0]);

    float acc[2][4][4];
#pragma unroll
    for (int mf = 0; mf < 2; ++mf)
#pragma unroll
        for (int nf = 0; nf < 4; ++nf)
#pragma unroll
            for (int i = 0; i < 4; ++i) acc[mf][nf][i] = 0.0f;

#define C2_LOAD(Q, BUF)                                                          \
    {                                                                            \
        int cc = (Q) * 4;                                                        \
        for (int idx = tid; idx < 2048; idx += 256) {                            \
            int oc = idx & 31, k = (idx >> 5) & 15, ci = idx >> 9;               \
            unsigned dst = sw_base + ((((BUF)*4 + ci) * 16 + k) * 33 + oc) * 4;  \
            cpa4(dst, w2 + (size_t)((ocb + oc) * 32 + cc + ci) * 16 + k, true);  \
        }                                                                        \
        for (int idx = tid; idx < 4752; idx += 256) {                            \
            int v = idx % 66, u = (idx / 66) % 18, ci = idx / 1188;              \
            int ih = 2 * oh0 - 1 + u, iw = -1 + v;                               \
            bool ok = (ih >= 0) && (ih < 128) && (iw >= 0) && (iw < 64);         \
            const float* src = ok ? in + (size_t)(cc + ci) * (128 * 64) + ih * 64 + iw : in; \
            unsigned dst = si_base + ((((BUF)*4 + ci) * 18 + u) * 66 + v) * 4;   \
            cpa4(dst, src, ok);                                                  \
        }                                                                        \
    }

    C2_LOAD(0, 0);
    CP_COMMIT();
    for (int q = 0; q < 8; ++q) {
        int buf = q & 1;
        if (q + 1 < 8) {
            C2_LOAD(q + 1, buf ^ 1);
            CP_COMMIT();
            CP_WAIT1();
        } else {
            CP_WAIT0();
        }
        __syncthreads();
#pragma unroll
        for (int ci = 0; ci < 4; ++ci) {
#pragma unroll
            for (int h = 0; h < 2; ++h) {
                int u0 = 2 * warp + 2 * h;
                unsigned a[2][4];
#pragma unroll
                for (int mf = 0; mf < 2; ++mf) {
                    int v0 = 32 * mf + 2 * r + c;
                    a[mf][0] = __float_as_uint(s_in[buf][ci][u0][v0]);
                    a[mf][1] = __float_as_uint(s_in[buf][ci][u0][v0 + 16]);
                    a[mf][2] = __float_as_uint(s_in[buf][ci][u0 + 1][v0]);
                    a[mf][3] = __float_as_uint(s_in[buf][ci][u0 + 1][v0 + 16]);
                }
#pragma unroll
                for (int nf = 0; nf < 4; ++nf) {
                    unsigned bfr[2];
                    bfr[0] = __float_as_uint(s_w[buf][ci][8 * h + c][8 * nf + r]);
                    bfr[1] = __float_as_uint(s_w[buf][ci][8 * h + c + 4][8 * nf + r]);
                    mma8(acc[0][nf], a[0], bfr);
                    mma8(acc[1][nf], a[1], bfr);
                }
            }
        }
        __syncthreads();
    }
    int oh = oh0 + warp;
#pragma unroll
    for (int mf = 0; mf < 2; ++mf) {
        int ow = 16 * mf + r;
#pragma unroll
        for (int nf = 0; nf < 4; ++nf) {
            int oc = ocb + 8 * nf + 2 * c;
            float bi0 = __ldg(b2 + oc), bi1 = __ldg(b2 + oc + 1);
            float* base = g_c2 + ((size_t)(g * 64 + oc) * 64 + oh) * 32;
            base[ow]           = fmaxf(acc[mf][nf][0] + bi0, 0.0f);
            (base + 2048)[ow]  = fmaxf(acc[mf][nf][1] + bi1, 0.0f);
            base[ow + 8]          = fmaxf(acc[mf][nf][2] + bi0, 0.0f);
            (base + 2048)[ow + 8] = fmaxf(acc[mf][nf][3] + bi1, 0.0f);
        }
    }
#undef C2_LOAD
}

// ---------------------------------------------------------------------------
// Kernel 4: conv3 64->64, 4x4, s2, p1 + ReLU, fused global mean pool.
// Block 256: tile oh16 x ow16(full) x 16oc. grid (2 oh, 4 ocg, 20).
// cp.async double-buffered over 16 ci-chunks. Register reduce -> atomicAdd.
// ---------------------------------------------------------------------------
__global__ __launch_bounds__(256) void k_conv3pool(const float* __restrict__ w3,
                                                   const float* __restrict__ b3) {
    __shared__ float s_in[2][4][34][34];
    __shared__ float s_w[2][4][16][17];

    int tid = threadIdx.x;
    int warp = tid >> 5, t = tid & 31;
    int r = t >> 2, c = t & 3;
    int oh0 = blockIdx.x * 16;
    int ocb = blockIdx.y * 16;
    int g = blockIdx.z;
    const float* in = g_c2 + (size_t)g * 64 * 64 * 32;

    unsigned si_base = (unsigned)__cvta_generic_to_shared(&s_in[0][0][0][0]);
    unsigned sw_base = (unsigned)__cvta_generic_to_shared(&s_w[0][0][0][0]);

    float acc[2][2][4];
#pragma unroll
    for (int mf = 0; mf < 2; ++mf)
#pragma unroll
        for (int nf = 0; nf < 2; ++nf)
#pragma unroll
            for (int i = 0; i < 4; ++i) acc[mf][nf][i] = 0.0f;

#define C3_LOAD(Q, BUF)                                                          \
    {                                                                            \
        int cc = (Q) * 4;                                                        \
        for (int idx = tid; idx < 1024; idx += 256) {                            \
            int oc = idx & 15, k = (idx >> 4) & 15, ci = idx >> 8;               \
            unsigned dst = sw_base + ((((BUF)*4 + ci) * 16 + k) * 17 + oc) * 4;  \
            cpa4(dst, w3 + (size_t)((ocb + oc) * 64 + cc + ci) * 16 + k, true);  \
        }                                                                        \
        for (int idx = tid; idx < 4624; idx += 256) {                            \
            int v = idx % 34, u = (idx / 34) % 34, ci = idx / 1156;              \
            int ih = 2 * oh0 - 1 + u, iw = -1 + v;                               \
            bool ok = (ih >= 0) && (ih < 64) && (iw >= 0) && (iw < 32);          \
            const float* src = ok ? in + (size_t)(cc + ci) * (64 * 32) + ih * 32 + iw : in; \
            unsigned dst = si_base + ((((BUF)*4 + ci) * 34 + u) * 34 + v) * 4;   \
            cpa4(dst, src, ok);                                                  \
        }                                                                        \
    }

    C3_LOAD(0, 0);
    CP_COMMIT();
    for (int q = 0; q < 16; ++q) {
        int buf = q & 1;
        if (q + 1 < 16) {
            C3_LOAD(q + 1, buf ^ 1);
            CP_COMMIT();
            CP_WAIT1();
        } else {
            CP_WAIT0();
        }
        __syncthreads();
#pragma unroll
        for (int ci = 0; ci < 4; ++ci) {
#pragma unroll
            for (int h = 0; h < 2; ++h) {
                unsigned a[2][4];
#pragma unroll
                for (int mf = 0; mf < 2; ++mf) {
                    int u0 = 4 * warp + 2 * mf + 2 * h;
                    int v0 = 2 * r + c;
                    a[mf][0] = __float_as_uint(s_in[buf][ci][u0][v0]);
                    a[mf][1] = __float_as_uint(s_in[buf][ci][u0][v0 + 16]);
                    a[mf][2] = __float_as_uint(s_in[buf][ci][u0 + 1][v0]);
                    a[mf][3] = __float_as_uint(s_in[buf][ci][u0 + 1][v0 + 16]);
                }
#pragma unroll
                for (int nf = 0; nf < 2; ++nf) {
                    unsigned bfr[2];
                    bfr[0] = __float_as_uint(s_w[buf][ci][8 * h + c][8 * nf + r]);
                    bfr[1] = __float_as_uint(s_w[buf][ci][8 * h + c + 4][8 * nf + r]);
                    mma8(acc[0][nf], a[0], bfr);
                    mma8(acc[1][nf], a[1], bfr);
                }
            }
        }
        __syncthreads();
    }
    // bias + relu + warp reduce -> atomicAdd
#pragma unroll
    for (int nf = 0; nf < 2; ++nf) {
        int oc0 = ocb + 8 * nf + 2 * c;
        float bi0 = __ldg(b3 + oc0), bi1 = __ldg(b3 + oc0 + 1);
        float s0 = 0.0f, s1 = 0.0f;
#pragma unroll
        for (int mf = 0; mf < 2; ++mf) {
            s0 += fmaxf(acc[mf][nf][0] + bi0, 0.0f) + fmaxf(acc[mf][nf][2] + bi0, 0.0f);
            s1 += fmaxf(acc[mf][nf][1] + bi1, 0.0f) + fmaxf(acc[mf][nf][3] + bi1, 0.0f);
        }
#pragma unroll
        for (int o = 4; o <= 16; o <<= 1) {
            s0 += __shfl_xor_sync(0xFFFFFFFFu, s0, o);
            s1 += __shfl_xor_sync(0xFFFFFFFFu, s1, o);
        }
        if (r == 0) {
            atomicAdd(&g_pool[g * 64 + oc0],     s0 * (1.0f / 512.0f));
            atomicAdd(&g_pool[g * 64 + oc0 + 1], s1 * (1.0f / 512.0f));
        }
    }
#undef C3_LOAD
}

// ---------------------------------------------------------------------------
// Kernel 5: key MLP 64->256->128->256 per image (grid 20, block 256)
// ---------------------------------------------------------------------------
__global__ __launch_bounds__(256) void k_keys(const float* __restrict__ f1w, const float* __restrict__ f1b,
                                              const float* __restrict__ f2w, const float* __restrict__ f2b,
                                              const float* __restrict__ f3w, const float* __restrict__ f3b) {
    __shared__ float p[64], h1[256], h2[128];
    int g = blockIdx.x, tid = threadIdx.x;
    if (tid < 64) p[tid] = g_pool[g * 64 + tid];
    __syncthreads();
    {
        float s = f1b[tid];
        const float* wr = f1w + (size_t)tid * 64;
#pragma unroll 8
        for (int c = 0; c < 64; ++c) s += wr[c] * p[c];
        h1[tid] = fmaxf(s, 0.0f);
    }
    __syncthreads();
    if (tid < 128) {
        float s = f2b[tid];
        const float* wr = f2w + (size_t)tid * 256;
#pragma unroll 8
        for (int c = 0; c < 256; ++c) s += wr[c] * h1[c];
        h2[tid] = fmaxf(s, 0.0f);
    }
    __syncthreads();
    {
        float s = f3b[tid];
        const float* wr = f3w + (size_t)tid * 128;
#pragma unroll 8
        for (int c = 0; c < 128; ++c) s += wr[c] * h2[c];
        g_keys[g * 256 + tid] = s;
    }
}

// ---------------------------------------------------------------------------
// Kernel 6: query MLP (image b*L), attn projection, softmax over L
// ---------------------------------------------------------------------------
__global__ __launch_bounds__(256) void k_attn(const float* __restrict__ f1w, const float* __restrict__ f1b,
                                              const float* __restrict__ f2w, const float* __restrict__ f2b,
                                              const float* __restrict__ f3w, const float* __restrict__ f3b,
                                              const float* __restrict__ aw, const float* __restrict__ ab) {
    __shared__ float p[64], h1[256], h2[128], qv[32], q[256], logits[8];
    int b = blockIdx.x, tid = threadIdx.x;
    int g0 = b * LL;
    if (tid < 64) p[tid] = g_pool[g0 * 64 + tid];
    __syncthreads();
    {
        float s = f1b[tid];
        const float* wr = f1w + (size_t)tid * 64;
#pragma unroll 8
        for (int c = 0; c < 64; ++c) s += wr[c] * p[c];
        h1[tid] = fmaxf(s, 0.0f);
    }
    __syncthreads();
    if (tid < 128) {
        float s = f2b[tid];
        const float* wr = f2w + (size_t)tid * 256;
#pragma unroll 8
        for (int c = 0; c < 256; ++c) s += wr[c] * h1[c];
        h2[tid] = fmaxf(s, 0.0f);
    }
    __syncthreads();
    if (tid < 32) {
        float s = f3b[tid];
        const float* wr = f3w + (size_t)tid * 128;
#pragma unroll 8
        for (int c = 0; c < 128; ++c) s += wr[c] * h2[c];
        qv[tid] = s;
    }
    __syncthreads();
    {
        float s = ab[tid];
        const float* wr = aw + (size_t)tid * 32;
#pragma unroll
        for (int j = 0; j < 32; ++j) s += wr[j] * qv[j];
        q[tid] = s;
    }
    __syncthreads();
    int wid = tid >> 5, lane = tid & 31;
    if (wid < LL) {
        const float* kr = g_keys + (size_t)(g0 + wid) * 256;
        float s = 0.0f;
        for (int i = lane; i < 256; i += 32) s += kr[i] * q[i];
#pragma unroll
        for (int o = 16; o; o >>= 1) s += __shfl_xor_sync(0xFFFFFFFFu, s, o);
        if (lane == 0) logits[wid] = s;
    }
    __syncthreads();
    if (tid == 0) {
        float m = -1e30f;
        for (int n = 0; n < LL; ++n) m = fmaxf(m, logits[n]);
        float e[LL];
        float den = 0.0f;
        for (int n = 0; n < LL; ++n) { e[n] = expf(logits[n] - m); den += e[n]; }
        float inv = 1.0f / den;
        for (int n = 0; n < LL; ++n) g_attn[b * LL + n] = e[n] * inv;
    }
}

// ---------------------------------------------------------------------------
// Kernel 7: out[b] = sum_n attn[b][n] * neigh[b*L+n]   (float4 vectorized)
// ---------------------------------------------------------------------------
__global__ __launch_bounds__(256) void k_fuse(float* __restrict__ out) {
    int b = blockIdx.y;
    int i = blockIdx.x * blockDim.x + threadIdx.x;
    float a0 = g_attn[b * LL + 0];
    float a1 = g_attn[b * LL + 1];
    float a2 = g_attn[b * LL + 2];
    float a3 = g_attn[b * LL + 3];
    float a4 = g_attn[b * LL + 4];
    const float4* n0 = reinterpret_cast<const float4*>(g_neigh + (size_t)(b * LL + 0) * CHW);
    const float4* n1 = reinterpret_cast<const float4*>(g_neigh + (size_t)(b * LL + 1) * CHW);
    const float4* n2 = reinterpret_cast<const float4*>(g_neigh + (size_t)(b * LL + 2) * CHW);
    const float4* n3 = reinterpret_cast<const float4*>(g_neigh + (size_t)(b * LL + 3) * CHW);
    const float4* n4 = reinterpret_cast<const float4*>(g_neigh + (size_t)(b * LL + 4) * CHW);
    float4 v0 = n0[i], v1 = n1[i], v2 = n2[i], v3 = n3[i], v4 = n4[i];
    float4 r;
    r.x = a0 * v0.x + a1 * v1.x + a2 * v2.x + a3 * v3.x + a4 * v4.x;
    r.y = a0 * v0.y + a1 * v1.y + a2 * v2.y + a3 * v3.y + a4 * v4.y;
    r.z = a0 * v0.z + a1 * v1.z + a2 * v2.z + a3 * v3.z + a4 * v4.z;
    r.w = a0 * v0.w + a1 * v1.w + a2 * v2.w + a3 * v3.w + a4 * v4.w;
    reinterpret_cast<float4*>(out + (size_t)b * CHW)[i] = r;
}

// ---------------------------------------------------------------------------
extern "C" void kernel_launch(void* const* d_in, const int* in_sizes, int n_in,
                              void* d_out, int out_size) {
    const float* x    = (const float*)d_in[0];
    const float* nam  = (const float*)d_in[2];
    const float* w1   = (const float*)d_in[3];
    const float* b1   = (const float*)d_in[4];
    const float* w2   = (const float*)d_in[5];
    const float* b2   = (const float*)d_in[6];
    const float* w3   = (const float*)d_in[7];
    const float* b3   = (const float*)d_in[8];
    const float* kf1w = (const float*)d_in[9];
    const float* kf1b = (const float*)d_in[10];
    const float* kf2w = (const float*)d_in[11];
    const float* kf2b = (const float*)d_in[12];
    const float* kf3w = (const float*)d_in[13];
    const float* kf3b = (const float*)d_in[14];
    const float* qf1w = (const float*)d_in[15];
    const float* qf1b = (const float*)d_in[16];
    const float* qf2w = (const float*)d_in[17];
    const float* qf2b = (const float*)d_in[18];
    const float* qf3w = (const float*)d_in[19];
    const float* qf3b = (const float*)d_in[20];
    const float* aw   = (const float*)d_in[21];
    const float* ab   = (const float*)d_in[22];
    float* out = (float*)d_out;

    k_zero     <<<5, 256>>>();
    k_warp     <<<dim3(HH, NIMG), 128>>>(x, nam);
    k_conv1    <<<dim3(32, NIMG), 256>>>(w1, b1);
    k_conv2    <<<dim3(8, 2, NIMG), 256>>>(w2, b2);
    k_conv3pool<<<dim3(2, 4, NIMG), 256>>>(w3, b3);
    k_keys     <<<NIMG, 256>>>(kf1w, kf1b, kf2w, kf2b, kf3w, kf3b);
    k_attn     <<<BB, 256>>>(qf1w, qf1b, qf2w, qf2b, qf3w, qf3b, aw, ab);
    k_fuse     <<<dim3(CHW / 4 / 256, BB), 256>>>(out);
}

// round 7
// speedup vs baseline: 3.5004x; 1.6510x over previous
#include <cuda_runtime.h>
#include <cuda_bf16.h>
#include <math.h>

// Problem dims
#define BB 4
#define LL 5
#define CIN 64
#define HH 256
#define WW 128
#define NIMG 20           // B*L
#define CHW (CIN*HH*WW)   // 2097152

// Scratch (static device globals; no allocation)
__device__ float g_neigh[NIMG * CIN * HH * WW];      // 20x64x256x128
__device__ float g_c1[NIMG * 32 * 128 * 64];
__device__ float g_c2[NIMG * 64 * 64 * 32];
__device__ float g_pool[NIMG * 64];
__device__ float g_keys[NIMG * 256];
__device__ float g_attn[BB * LL];

// ---------------- tf32 mma + cp.async helpers ------------------------------
__device__ __forceinline__ void mma8(float* d, const unsigned* a, const unsigned* b) {
    asm volatile(
        "mma.sync.aligned.m16n8k8.row.col.f32.tf32.tf32.f32 "
        "{%0,%1,%2,%3},{%4,%5,%6,%7},{%8,%9},{%0,%1,%2,%3};"
        : "+f"(d[0]), "+f"(d[1]), "+f"(d[2]), "+f"(d[3])
        : "r"(a[0]), "r"(a[1]), "r"(a[2]), "r"(a[3]), "r"(b[0]), "r"(b[1]));
}
__device__ __forceinline__ void cpa16(unsigned dst, const float* src, bool ok) {
    asm volatile("cp.async.cg.shared.global [%0], [%1], 16, %2;"
                 :: "r"(dst), "l"(src), "r"(ok ? 16 : 0));
}
#define CP_COMMIT() asm volatile("cp.async.commit_group;")
#define CP_WAIT1()  asm volatile("cp.async.wait_group 1;")
#define CP_WAIT0()  asm volatile("cp.async.wait_group 0;")

// ---------------------------------------------------------------------------
// Kernel 1: affine grid + bilinear grid_sample (zero padding) -> g_neigh
// ---------------------------------------------------------------------------
__global__ __launch_bounds__(128) void k_warp(const float* __restrict__ x,
                                              const float* __restrict__ nam) {
    int w = threadIdx.x;
    int h = blockIdx.x;
    int g = blockIdx.y;
    int b = g / LL, n = g % LL;
    const float* th = nam + ((size_t)(b * LL + 0) * LL + n) * 6;
    float t00 = th[0], t01 = th[1], t02 = th[2];
    float t10 = th[3], t11 = th[4], t12 = th[5];

    float gx = (w + 0.5f) * (2.0f / WW) - 1.0f;
    float gy = (h + 0.5f) * (2.0f / HH) - 1.0f;
    float gxx = t00 * gx + t01 * gy + t02;
    float gyy = t10 * gx + t11 * gy + t12;

    float xf = ((gxx + 1.0f) * WW - 1.0f) * 0.5f;
    float yf = ((gyy + 1.0f) * HH - 1.0f) * 0.5f;
    float x0f = floorf(xf), y0f = floorf(yf);
    int x0 = (int)x0f, y0 = (int)y0f;
    int x1 = x0 + 1, y1 = y0 + 1;
    float wx1 = xf - x0f, wy1 = yf - y0f;
    float wx0 = 1.0f - wx1, wy0 = 1.0f - wy1;

    bool vx0 = (x0 >= 0) & (x0 < WW), vx1 = (x1 >= 0) & (x1 < WW);
    bool vy0 = (y0 >= 0) & (y0 < HH), vy1 = (y1 >= 0) & (y1 < HH);
    int cx0 = min(max(x0, 0), WW - 1), cx1 = min(max(x1, 0), WW - 1);
    int cy0 = min(max(y0, 0), HH - 1), cy1 = min(max(y1, 0), HH - 1);

    float w00 = wx0 * wy0 * (float)(vx0 && vy0);
    float w10 = wx1 * wy0 * (float)(vx1 && vy0);
    float w01 = wx0 * wy1 * (float)(vx0 && vy1);
    float w11 = wx1 * wy1 * (float)(vx1 && vy1);

    int a00 = cy0 * WW + cx0;
    int a10 = cy0 * WW + cx1;
    int a01 = cy1 * WW + cx0;
    int a11 = cy1 * WW + cx1;

    const float* img = x + (size_t)g * CHW;
    float* outp = g_neigh + (size_t)g * CHW + h * WW + w;
#pragma unroll 8
    for (int c = 0; c < CIN; ++c) {
        const float* ic = img + c * (HH * WW);
        float v = w00 * __ldg(ic + a00) + w10 * __ldg(ic + a10) +
                  w01 * __ldg(ic + a01) + w11 * __ldg(ic + a11);
        outp[c * (HH * WW)] = v;
    }
}

// ---------------------------------------------------------------------------
__global__ void k_zero() {
    int i = blockIdx.x * blockDim.x + threadIdx.x;
    if (i < NIMG * 64) g_pool[i] = 0.0f;
}

// ---------------------------------------------------------------------------
// Kernel 2: conv1 64->32, 4x4, s2, p1, ReLU.  256x128 -> 128x64
// tf32 implicit GEMM, float4 cp.async double-buffered over 16 ci-chunks.
// Block 256 (8 warps): tile oh8 x ow32 x 32oc. grid (32, 20).
// Input tile: rows 18, cols 72 floats starting at iw = 2*ow0-4 (16B aligned,
// boundary float4s always fully valid or fully OOB). Weights [ci][oc][k pad20].
// ---------------------------------------------------------------------------
__global__ __launch_bounds__(256) void k_conv1(const float* __restrict__ w1,
                                               const float* __restrict__ b1) {
    __shared__ float s_in[2][4][18][72];
    __shared__ float s_w[2][4][32][20];

    int tid = threadIdx.x;
    int warp = tid >> 5, t = tid & 31;
    int r = t >> 2, c = t & 3;
    int tile = blockIdx.x;
    int g = blockIdx.y;
    int oh0 = (tile >> 1) * 8;
    int ow0 = (tile & 1) * 32;
    const float* in = g_neigh + (size_t)g * CHW;

    unsigned si_base = (unsigned)__cvta_generic_to_shared(&s_in[0][0][0][0]);
    unsigned sw_base = (unsigned)__cvta_generic_to_shared(&s_w[0][0][0][0]);

    float acc[2][4][4];
#pragma unroll
    for (int mf = 0; mf < 2; ++mf)
#pragma unroll
        for (int nf = 0; nf < 4; ++nf)
#pragma unroll
            for (int i = 0; i < 4; ++i) acc[mf][nf][i] = 0.0f;

#define C1_LOAD(Q, BUF)                                                          \
    {                                                                            \
        int cc = (Q) * 4;                                                        \
        for (int idx = tid; idx < 512; idx += 256) {                             \
            int quad = idx & 3, oc = (idx >> 2) & 31, ci = idx >> 7;             \
            unsigned dst = sw_base + ((((BUF)*4 + ci) * 32 + oc) * 20 + quad * 4) * 4; \
            cpa16(dst, w1 + (size_t)(oc * 64 + cc + ci) * 16 + quad * 4, true);  \
        }                                                                        \
        for (int idx = tid; idx < 1296; idx += 256) {                            \
            int v4 = idx % 18, u = (idx / 18) % 18, ci = idx / 324;              \
            int ih = 2 * oh0 - 1 + u, iw0 = 2 * ow0 - 4 + 4 * v4;                \
            bool ok = (ih >= 0) && (ih < HH) && (iw0 >= 0) && (iw0 + 3 < WW);    \
            const float* src = ok ? in + (size_t)(cc + ci) * (HH * WW) + ih * WW + iw0 : in; \
            unsigned dst = si_base + ((((BUF)*4 + ci) * 18 + u) * 72 + 4 * v4) * 4; \
            cpa16(dst, src, ok);                                                 \
        }                                                                        \
    }

    C1_LOAD(0, 0);
    CP_COMMIT();
    for (int q = 0; q < 16; ++q) {
        int buf = q & 1;
        if (q + 1 < 16) {
            C1_LOAD(q + 1, buf ^ 1);
            CP_COMMIT();
            CP_WAIT1();
        } else {
            CP_WAIT0();
        }
        __syncthreads();
#pragma unroll
        for (int ci = 0; ci < 4; ++ci) {
#pragma unroll
            for (int h = 0; h < 2; ++h) {
                int u0 = 2 * warp + 2 * h;
                unsigned a[2][4];
#pragma unroll
                for (int mf = 0; mf < 2; ++mf) {
                    int v0 = 32 * mf + 2 * r + c + 3;   // +3: tile starts at iw-4 vs iw-1
                    a[mf][0] = __float_as_uint(s_in[buf][ci][u0][v0]);
                    a[mf][1] = __float_as_uint(s_in[buf][ci][u0][v0 + 16]);
                    a[mf][2] = __float_as_uint(s_in[buf][ci][u0 + 1][v0]);
                    a[mf][3] = __float_as_uint(s_in[buf][ci][u0 + 1][v0 + 16]);
                }
#pragma unroll
                for (int nf = 0; nf < 4; ++nf) {
                    unsigned bfr[2];
                    bfr[0] = __float_as_uint(s_w[buf][ci][8 * nf + r][8 * h + c]);
                    bfr[1] = __float_as_uint(s_w[buf][ci][8 * nf + r][8 * h + c + 4]);
                    mma8(acc[0][nf], a[0], bfr);
                    mma8(acc[1][nf], a[1], bfr);
                }
            }
        }
        __syncthreads();
    }
    int oh = oh0 + warp;
#pragma unroll
    for (int mf = 0; mf < 2; ++mf) {
        int ow = ow0 + 16 * mf + r;
#pragma unroll
        for (int nf = 0; nf < 4; ++nf) {
            int oc = 8 * nf + 2 * c;
            float bi0 = __ldg(b1 + oc), bi1 = __ldg(b1 + oc + 1);
            float* base = g_c1 + ((size_t)(g * 32 + oc) * 128 + oh) * 64;
            base[ow]           = fmaxf(acc[mf][nf][0] + bi0, 0.0f);
            (base + 8192)[ow]  = fmaxf(acc[mf][nf][1] + bi1, 0.0f);
            base[ow + 8]          = fmaxf(acc[mf][nf][2] + bi0, 0.0f);
            (base + 8192)[ow + 8] = fmaxf(acc[mf][nf][3] + bi1, 0.0f);
        }
    }
#undef C1_LOAD
}

// ---------------------------------------------------------------------------
// Kernel 3: conv2 32->64, 4x4, s2, p1, ReLU.  128x64 -> 64x32
// Block 256: tile oh8 x ow32(full) x 32oc. grid (8 oh, 2 ocg, 20).
// float4 cp.async double-buffered over 8 ci-chunks.
// ---------------------------------------------------------------------------
__global__ __launch_bounds__(256) void k_conv2(const float* __restrict__ w2,
                                               const float* __restrict__ b2) {
    __shared__ float s_in[2][4][18][72];
    __shared__ float s_w[2][4][32][20];

    int tid = threadIdx.x;
    int warp = tid >> 5, t = tid & 31;
    int r = t >> 2, c = t & 3;
    int oh0 = blockIdx.x * 8;
    int ocb = blockIdx.y * 32;
    int g = blockIdx.z;
    const float* in = g_c1 + (size_t)g * 32 * 128 * 64;

    unsigned si_base = (unsigned)__cvta_generic_to_shared(&s_in[0][0][0][0]);
    unsigned sw_base = (unsigned)__cvta_generic_to_shared(&s_w[0][0][0][0]);

    float acc[2][4][4];
#pragma unroll
    for (int mf = 0; mf < 2; ++mf)
#pragma unroll
        for (int nf = 0; nf < 4; ++nf)
#pragma unroll
            for (int i = 0; i < 4; ++i) acc[mf][nf][i] = 0.0f;

#define C2_LOAD(Q, BUF)                                                          \
    {                                                                            \
        int cc = (Q) * 4;                                                        \
        for (int idx = tid; idx < 512; idx += 256) {                             \
            int quad = idx & 3, oc = (idx >> 2) & 31, ci = idx >> 7;             \
            unsigned dst = sw_base + ((((BUF)*4 + ci) * 32 + oc) * 20 + quad * 4) * 4; \
            cpa16(dst, w2 + (size_t)((ocb + oc) * 32 + cc + ci) * 16 + quad * 4, true); \
        }                                                                        \
        for (int idx = tid; idx < 1296; idx += 256) {                            \
            int v4 = idx % 18, u = (idx / 18) % 18, ci = idx / 324;              \
            int ih = 2 * oh0 - 1 + u, iw0 = -4 + 4 * v4;                         \
            bool ok = (ih >= 0) && (ih < 128) && (iw0 >= 0) && (iw0 + 3 < 64);   \
            const float* src = ok ? in + (size_t)(cc + ci) * (128 * 64) + ih * 64 + iw0 : in; \
            unsigned dst = si_base + ((((BUF)*4 + ci) * 18 + u) * 72 + 4 * v4) * 4; \
            cpa16(dst, src, ok);                                                 \
        }                                                                        \
    }

    C2_LOAD(0, 0);
    CP_COMMIT();
    for (int q = 0; q < 8; ++q) {
        int buf = q & 1;
        if (q + 1 < 8) {
            C2_LOAD(q + 1, buf ^ 1);
            CP_COMMIT();
            CP_WAIT1();
        } else {
            CP_WAIT0();
        }
        __syncthreads();
#pragma unroll
        for (int ci = 0; ci < 4; ++ci) {
#pragma unroll
            for (int h = 0; h < 2; ++h) {
                int u0 = 2 * warp + 2 * h;
                unsigned a[2][4];
#pragma unroll
                for (int mf = 0; mf < 2; ++mf) {
                    int v0 = 32 * mf + 2 * r + c + 3;
                    a[mf][0] = __float_as_uint(s_in[buf][ci][u0][v0]);
                    a[mf][1] = __float_as_uint(s_in[buf][ci][u0][v0 + 16]);
                    a[mf][2] = __float_as_uint(s_in[buf][ci][u0 + 1][v0]);
                    a[mf][3] = __float_as_uint(s_in[buf][ci][u0 + 1][v0 + 16]);
                }
#pragma unroll
                for (int nf = 0; nf < 4; ++nf) {
                    unsigned bfr[2];
                    bfr[0] = __float_as_uint(s_w[buf][ci][8 * nf + r][8 * h + c]);
                    bfr[1] = __float_as_uint(s_w[buf][ci][8 * nf + r][8 * h + c + 4]);
                    mma8(acc[0][nf], a[0], bfr);
                    mma8(acc[1][nf], a[1], bfr);
                }
            }
        }
        __syncthreads();
    }
    int oh = oh0 + warp;
#pragma unroll
    for (int mf = 0; mf < 2; ++mf) {
        int ow = 16 * mf + r;
#pragma unroll
        for (int nf = 0; nf < 4; ++nf) {
            int oc = ocb + 8 * nf + 2 * c;
            float bi0 = __ldg(b2 + oc), bi1 = __ldg(b2 + oc + 1);
            float* base = g_c2 + ((size_t)(g * 64 + oc) * 64 + oh) * 32;
            base[ow]           = fmaxf(acc[mf][nf][0] + bi0, 0.0f);
            (base + 2048)[ow]  = fmaxf(acc[mf][nf][1] + bi1, 0.0f);
            base[ow + 8]          = fmaxf(acc[mf][nf][2] + bi0, 0.0f);
            (base + 2048)[ow + 8] = fmaxf(acc[mf][nf][3] + bi1, 0.0f);
        }
    }
#undef C2_LOAD
}

// ---------------------------------------------------------------------------
// Kernel 4: conv3 64->64, 4x4, s2, p1 + ReLU, fused global mean pool.
// Block 256: tile oh16 x ow16(full) x 16oc. grid (2 oh, 4 ocg, 20).
// float4 cp.async double-buffered over 16 ci-chunks. Reg reduce -> atomicAdd.
// ---------------------------------------------------------------------------
__global__ __launch_bounds__(256) void k_conv3pool(const float* __restrict__ w3,
                                                   const float* __restrict__ b3) {
    __shared__ float s_in[2][4][34][40];
    __shared__ float s_w[2][4][16][20];

    int tid = threadIdx.x;
    int warp = tid >> 5, t = tid & 31;
    int r = t >> 2, c = t & 3;
    int oh0 = blockIdx.x * 16;
    int ocb = blockIdx.y * 16;
    int g = blockIdx.z;
    const float* in = g_c2 + (size_t)g * 64 * 64 * 32;

    unsigned si_base = (unsigned)__cvta_generic_to_shared(&s_in[0][0][0][0]);
    unsigned sw_base = (unsigned)__cvta_generic_to_shared(&s_w[0][0][0][0]);

    float acc[2][2][4];
#pragma unroll
    for (int mf = 0; mf < 2; ++mf)
#pragma unroll
        for (int nf = 0; nf < 2; ++nf)
#pragma unroll
            for (int i = 0; i < 4; ++i) acc[mf][nf][i] = 0.0f;

#define C3_LOAD(Q, BUF)                                                          \
    {                                                                            \
        int cc = (Q) * 4;                                                        \
        for (int idx = tid; idx < 256; idx += 256) {                             \
            int quad = idx & 3, oc = (idx >> 2) & 15, ci = idx >> 6;             \
            unsigned dst = sw_base + ((((BUF)*4 + ci) * 16 + oc) * 20 + quad * 4) * 4; \
            cpa16(dst, w3 + (size_t)((ocb + oc) * 64 + cc + ci) * 16 + quad * 4, true); \
        }                                                                        \
        for (int idx = tid; idx < 1360; idx += 256) {                            \
            int v4 = idx % 10, u = (idx / 10) % 34, ci = idx / 340;              \
            int ih = 2 * oh0 - 1 + u, iw0 = -4 + 4 * v4;                         \
            bool ok = (ih >= 0) && (ih < 64) && (iw0 >= 0) && (iw0 + 3 < 32);    \
            const float* src = ok ? in + (size_t)(cc + ci) * (64 * 32) + ih * 32 + iw0 : in; \
            unsigned dst = si_base + ((((BUF)*4 + ci) * 34 + u) * 40 + 4 * v4) * 4; \
            cpa16(dst, src, ok);                                                 \
        }                                                                        \
    }

    C3_LOAD(0, 0);
    CP_COMMIT();
    for (int q = 0; q < 16; ++q) {
        int buf = q & 1;
        if (q + 1 < 16) {
            C3_LOAD(q + 1, buf ^ 1);
            CP_COMMIT();
            CP_WAIT1();
        } else {
            CP_WAIT0();
        }
        __syncthreads();
#pragma unroll
        for (int ci = 0; ci < 4; ++ci) {
#pragma unroll
            for (int h = 0; h < 2; ++h) {
                unsigned a[2][4];
#pragma unroll
                for (int mf = 0; mf < 2; ++mf) {
                    int u0 = 4 * warp + 2 * mf + 2 * h;
                    int v0 = 2 * r + c + 3;
                    a[mf][0] = __float_as_uint(s_in[buf][ci][u0][v0]);
                    a[mf][1] = __float_as_uint(s_in[buf][ci][u0][v0 + 16]);
                    a[mf][2] = __float_as_uint(s_in[buf][ci][u0 + 1][v0]);
                    a[mf][3] = __float_as_uint(s_in[buf][ci][u0 + 1][v0 + 16]);
                }
#pragma unroll
                for (int nf = 0; nf < 2; ++nf) {
                    unsigned bfr[2];
                    bfr[0] = __float_as_uint(s_w[buf][ci][8 * nf + r][8 * h + c]);
                    bfr[1] = __float_as_uint(s_w[buf][ci][8 * nf + r][8 * h + c + 4]);
                    mma8(acc[0][nf], a[0], bfr);
                    mma8(acc[1][nf], a[1], bfr);
                }
            }
        }
        __syncthreads();
    }
    // bias + relu + warp reduce -> atomicAdd
#pragma unroll
    for (int nf = 0; nf < 2; ++nf) {
        int oc0 = ocb + 8 * nf + 2 * c;
        float bi0 = __ldg(b3 + oc0), bi1 = __ldg(b3 + oc0 + 1);
        float s0 = 0.0f, s1 = 0.0f;
#pragma unroll
        for (int mf = 0; mf < 2; ++mf) {
            s0 += fmaxf(acc[mf][nf][0] + bi0, 0.0f) + fmaxf(acc[mf][nf][2] + bi0, 0.0f);
            s1 += fmaxf(acc[mf][nf][1] + bi1, 0.0f) + fmaxf(acc[mf][nf][3] + bi1, 0.0f);
        }
#pragma unroll
        for (int o = 4; o <= 16; o <<= 1) {
            s0 += __shfl_xor_sync(0xFFFFFFFFu, s0, o);
            s1 += __shfl_xor_sync(0xFFFFFFFFu, s1, o);
        }
        if (r == 0) {
            atomicAdd(&g_pool[g * 64 + oc0],     s0 * (1.0f / 512.0f));
            atomicAdd(&g_pool[g * 64 + oc0 + 1], s1 * (1.0f / 512.0f));
        }
    }
#undef C3_LOAD
}

// ---------------------------------------------------------------------------
// Kernel 5: key MLP 64->256->128->256 per image (grid 20, block 256)
// ---------------------------------------------------------------------------
__global__ __launch_bounds__(256) void k_keys(const float* __restrict__ f1w, const float* __restrict__ f1b,
                                              const float* __restrict__ f2w, const float* __restrict__ f2b,
                                              const float* __restrict__ f3w, const float* __restrict__ f3b) {
    __shared__ float p[64], h1[256], h2[128];
    int g = blockIdx.x, tid = threadIdx.x;
    if (tid < 64) p[tid] = g_pool[g * 64 + tid];
    __syncthreads();
    {
        float s = f1b[tid];
        const float* wr = f1w + (size_t)tid * 64;
#pragma unroll 8
        for (int c = 0; c < 64; ++c) s += wr[c] * p[c];
        h1[tid] = fmaxf(s, 0.0f);
    }
    __syncthreads();
    if (tid < 128) {
        float s = f2b[tid];
        const float* wr = f2w + (size_t)tid * 256;
#pragma unroll 8
        for (int c = 0; c < 256; ++c) s += wr[c] * h1[c];
        h2[tid] = fmaxf(s, 0.0f);
    }
    __syncthreads();
    {
        float s = f3b[tid];
        const float* wr = f3w + (size_t)tid * 128;
#pragma unroll 8
        for (int c = 0; c < 128; ++c) s += wr[c] * h2[c];
        g_keys[g * 256 + tid] = s;
    }
}

// ---------------------------------------------------------------------------
// Kernel 6: query MLP (image b*L), attn projection, softmax over L
// ---------------------------------------------------------------------------
__global__ __launch_bounds__(256) void k_attn(const float* __restrict__ f1w, const float* __restrict__ f1b,
                                              const float* __restrict__ f2w, const float* __restrict__ f2b,
                                              const float* __restrict__ f3w, const float* __restrict__ f3b,
                                              const float* __restrict__ aw, const float* __restrict__ ab) {
    __shared__ float p[64], h1[256], h2[128], qv[32], q[256], logits[8];
    int b = blockIdx.x, tid = threadIdx.x;
    int g0 = b * LL;
    if (tid < 64) p[tid] = g_pool[g0 * 64 + tid];
    __syncthreads();
    {
        float s = f1b[tid];
        const float* wr = f1w + (size_t)tid * 64;
#pragma unroll 8
        for (int c = 0; c < 64; ++c) s += wr[c] * p[c];
        h1[tid] = fmaxf(s, 0.0f);
    }
    __syncthreads();
    if (tid < 128) {
        float s = f2b[tid];
        const float* wr = f2w + (size_t)tid * 256;
#pragma unroll 8
        for (int c = 0; c < 256; ++c) s += wr[c] * h1[c];
        h2[tid] = fmaxf(s, 0.0f);
    }
    __syncthreads();
    if (tid < 32) {
        float s = f3b[tid];
        const float* wr = f3w + (size_t)tid * 128;
#pragma unroll 8
        for (int c = 0; c < 128; ++c) s += wr[c] * h2[c];
        qv[tid] = s;
    }
    __syncthreads();
    {
        float s = ab[tid];
        const float* wr = aw + (size_t)tid * 32;
#pragma unroll
        for (int j = 0; j < 32; ++j) s += wr[j] * qv[j];
        q[tid] = s;
    }
    __syncthreads();
    int wid = tid >> 5, lane = tid & 31;
    if (wid < LL) {
        const float* kr = g_keys + (size_t)(g0 + wid) * 256;
        float s = 0.0f;
        for (int i = lane; i < 256; i += 32) s += kr[i] * q[i];
#pragma unroll
        for (int o = 16; o; o >>= 1) s += __shfl_xor_sync(0xFFFFFFFFu, s, o);
        if (lane == 0) logits[wid] = s;
    }
    __syncthreads();
    if (tid == 0) {
        float m = -1e30f;
        for (int n = 0; n < LL; ++n) m = fmaxf(m, logits[n]);
        float e[LL];
        float den = 0.0f;
        for (int n = 0; n < LL; ++n) { e[n] = expf(logits[n] - m); den += e[n]; }
        float inv = 1.0f / den;
        for (int n = 0; n < LL; ++n) g_attn[b * LL + n] = e[n] * inv;
    }
}

// ---------------------------------------------------------------------------
// Kernel 7: out[b] = sum_n attn[b][n] * neigh[b*L+n]   (float4 vectorized)
// ---------------------------------------------------------------------------
__global__ __launch_bounds__(256) void k_fuse(float* __restrict__ out) {
    int b = blockIdx.y;
    int i = blockIdx.x * blockDim.x + threadIdx.x;
    float a0 = g_attn[b * LL + 0];
    float a1 = g_attn[b * LL + 1];
    float a2 = g_attn[b * LL + 2];
    float a3 = g_attn[b * LL + 3];
    float a4 = g_attn[b * LL + 4];
    const float4* n0 = reinterpret_cast<const float4*>(g_neigh + (size_t)(b * LL + 0) * CHW);
    const float4* n1 = reinterpret_cast<const float4*>(g_neigh + (size_t)(b * LL + 1) * CHW);
    const float4* n2 = reinterpret_cast<const float4*>(g_neigh + (size_t)(b * LL + 2) * CHW);
    const float4* n3 = reinterpret_cast<const float4*>(g_neigh + (size_t)(b * LL + 3) * CHW);
    const float4* n4 = reinterpret_cast<const float4*>(g_neigh + (size_t)(b * LL + 4) * CHW);
    float4 v0 = n0[i], v1 = n1[i], v2 = n2[i], v3 = n3[i], v4 = n4[i];
    float4 r;
    r.x = a0 * v0.x + a1 * v1.x + a2 * v2.x + a3 * v3.x + a4 * v4.x;
    r.y = a0 * v0.y + a1 * v1.y + a2 * v2.y + a3 * v3.y + a4 * v4.y;
    r.z = a0 * v0.z + a1 * v1.z + a2 * v2.z + a3 * v3.z + a4 * v4.z;
    r.w = a0 * v0.w + a1 * v1.w + a2 * v2.w + a3 * v3.w + a4 * v4.w;
    reinterpret_cast<float4*>(out + (size_t)b * CHW)[i] = r;
}

// ---------------------------------------------------------------------------
extern "C" void kernel_launch(void* const* d_in, const int* in_sizes, int n_in,
                              void* d_out, int out_size) {
    const float* x    = (const float*)d_in[0];
    const float* nam  = (const float*)d_in[2];
    const float* w1   = (const float*)d_in[3];
    const float* b1   = (const float*)d_in[4];
    const float* w2   = (const float*)d_in[5];
    const float* b2   = (const float*)d_in[6];
    const float* w3   = (const float*)d_in[7];
    const float* b3   = (const float*)d_in[8];
    const float* kf1w = (const float*)d_in[9];
    const float* kf1b = (const float*)d_in[10];
    const float* kf2w = (const float*)d_in[11];
    const float* kf2b = (const float*)d_in[12];
    const float* kf3w = (const float*)d_in[13];
    const float* kf3b = (const float*)d_in[14];
    const float* qf1w = (const float*)d_in[15];
    const float* qf1b = (const float*)d_in[16];
    const float* qf2w = (const float*)d_in[17];
    const float* qf2b = (const float*)d_in[18];
    const float* qf3w = (const float*)d_in[19];
    const float* qf3b = (const float*)d_in[20];
    const float* aw   = (const float*)d_in[21];
    const float* ab   = (const float*)d_in[22];
    float* out = (float*)d_out;

    k_zero     <<<5, 256>>>();
    k_warp     <<<dim3(HH, NIMG), 128>>>(x, nam);
    k_conv1    <<<dim3(32, NIMG), 256>>>(w1, b1);
    k_conv2    <<<dim3(8, 2, NIMG), 256>>>(w2, b2);
    k_conv3pool<<<dim3(2, 4, NIMG), 256>>>(w3, b3);
    k_keys     <<<NIMG, 256>>>(kf1w, kf1b, kf2w, kf2b, kf3w, kf3b);
    k_attn     <<<BB, 256>>>(qf1w, qf1b, qf2w, qf2b, qf3w, qf3b, aw, ab);
    k_fuse     <<<dim3(CHW / 4 / 256, BB), 256>>>(out);
}